// round 1
// baseline (speedup 1.0000x reference)
#include <cuda_runtime.h>
#include <math.h>
#include <stdint.h>

#define N0   4096
#define EDGES 65536
#define HID  128

// ---------------- device global scratch (no allocations allowed) ----------------
__device__ float dA0[(size_t)N0 * N0];         // 64 MB
__device__ float dA1[(size_t)2048 * 2048];     // 16 MB
__device__ float dA2[(size_t)1024 * 1024];     // 4 MB
__device__ float dA3[(size_t)512 * 512];
__device__ float dA4[(size_t)256 * 256];
__device__ float dPbuf[(size_t)2048 * 4096];   // gathered rows  B[perm,:]  (k x n), 32 MB
__device__ float dQbuf[(size_t)4096 * 2048];   // gathered cols  B[:,perm]  (n x k), 32 MB
__device__ float dX0[N0 * HID];
__device__ float dX1[2048 * HID];
__device__ float dX2[1024 * HID];
__device__ float dX3[512 * HID];
__device__ float dHa[N0 * HID];
__device__ float dHb[N0 * HID];
__device__ float dT1[N0 * HID];   // h@W
__device__ float dT2[N0 * HID];   // dis * (h@W)
__device__ float dT3[N0 * HID];   // A @ T2
__device__ float dDis[N0];
__device__ float dScore[N0];
__device__ float dVals[N0];
__device__ float dHWo[N0];
__device__ float dGv[N0];
__device__ int   dPerm0[2048];
__device__ int   dPerm1[1024];
__device__ int   dPerm2[512];
__device__ int   dPerm3[256];
__device__ float dPn[4];

// ---------------- kernels ----------------

__global__ void k_zero(float* p, size_t n) {
    size_t i = (size_t)blockIdx.x * blockDim.x + threadIdx.x;
    size_t stride = (size_t)gridDim.x * blockDim.x;
    for (; i < n; i += stride) p[i] = 0.0f;
}

__global__ void k_build_adj(const int* __restrict__ ei, float* __restrict__ A) {
    int e = blockIdx.x * blockDim.x + threadIdx.x;
    if (e < EDGES) {
        int s = ei[e];           // edge_index[0, e] = src
        int d = ei[EDGES + e];   // edge_index[1, e] = dst
        atomicAdd(&A[(size_t)d * N0 + s], 1.0f);
    }
}

__global__ void k_encoder(const float* __restrict__ x, const float* __restrict__ W,
                          const float* __restrict__ b, float* __restrict__ h) {
    int i = blockIdx.x;
    int c = threadIdx.x;
    float acc = b[c];
#pragma unroll
    for (int k = 0; k < 16; k++) acc += x[i * 16 + k] * W[k * HID + c];
    h[i * HID + c] = acc;
}

// Generic register-blocked SGEMM: C[M,N] = A[M,K] @ B[K,N], row-major.
// If zeroDiag, C[m,n] = 0 when m==n (augment: remove self loops of the submatrix).
template <int BM, int BN, int BK, int TM, int TN>
__global__ void k_gemm(const float* __restrict__ A, const float* __restrict__ B,
                       float* __restrict__ C, int M, int N, int K, int zeroDiag) {
    __shared__ float As[BK][BM];
    __shared__ float Bs[BK][BN];
    const int NT = (BM / TM) * (BN / TN);
    int tid = threadIdx.x;
    int m0 = blockIdx.y * BM, n0 = blockIdx.x * BN;
    int tm = (tid / (BN / TN)) * TM;
    int tn = (tid % (BN / TN)) * TN;
    float acc[TM][TN];
#pragma unroll
    for (int a = 0; a < TM; a++)
#pragma unroll
        for (int b = 0; b < TN; b++) acc[a][b] = 0.0f;

    for (int k0 = 0; k0 < K; k0 += BK) {
        for (int i = tid; i < BM * BK; i += NT) {
            int mm = i / BK, kk = i % BK;
            int gm = m0 + mm, gk = k0 + kk;
            As[kk][mm] = (gm < M && gk < K) ? A[(size_t)gm * K + gk] : 0.0f;
        }
        for (int i = tid; i < BK * BN; i += NT) {
            int kk = i / BN, nn = i % BN;
            int gk = k0 + kk, gn = n0 + nn;
            Bs[kk][nn] = (gk < K && gn < N) ? B[(size_t)gk * N + gn] : 0.0f;
        }
        __syncthreads();
#pragma unroll
        for (int kk = 0; kk < BK; kk++) {
            float ar[TM], br[TN];
#pragma unroll
            for (int a = 0; a < TM; a++) ar[a] = As[kk][tm + a];
#pragma unroll
            for (int b = 0; b < TN; b++) br[b] = Bs[kk][tn + b];
#pragma unroll
            for (int a = 0; a < TM; a++)
#pragma unroll
                for (int b = 0; b < TN; b++) acc[a][b] += ar[a] * br[b];
        }
        __syncthreads();
    }
#pragma unroll
    for (int a = 0; a < TM; a++)
#pragma unroll
        for (int b = 0; b < TN; b++) {
            int gm = m0 + tm + a, gn = n0 + tn + b;
            if (gm < M && gn < N) {
                float v = acc[a][b];
                if (zeroDiag && gm == gn) v = 0.0f;
                C[(size_t)gm * N + gn] = v;
            }
        }
}

// P[r, m] = B[perm[r], m] where B = offdiag(A) + I
__global__ void k_gather_rows(const float* __restrict__ A, const int* __restrict__ perm,
                              float* __restrict__ P, int k, int n) {
    size_t idx = (size_t)blockIdx.x * blockDim.x + threadIdx.x;
    if (idx < (size_t)k * n) {
        int r = (int)(idx / n), m = (int)(idx % n);
        int pr = perm[r];
        float v = A[(size_t)pr * n + m];
        P[idx] = (m == pr) ? 1.0f : v;
    }
}

// Q[m, c] = B[m, perm[c]] where B = offdiag(A) + I
__global__ void k_gather_cols(const float* __restrict__ A, const int* __restrict__ perm,
                              float* __restrict__ Q, int k, int n) {
    size_t idx = (size_t)blockIdx.x * blockDim.x + threadIdx.x;
    if (idx < (size_t)n * k) {
        int m = (int)(idx / k), c = (int)(idx % k);
        int pc = perm[c];
        float v = A[(size_t)m * n + pc];
        Q[idx] = (m == pc) ? 1.0f : v;
    }
}

// dis[i] = rsqrt(rowsum(A[i,:]) + 2)
__global__ void k_dis(const float* __restrict__ A, float* __restrict__ dis, int n) {
    int i = blockIdx.x;
    float s = 0.0f;
    for (int j = threadIdx.x; j < n; j += blockDim.x) s += A[(size_t)i * n + j];
    __shared__ float sm[256];
    sm[threadIdx.x] = s;
    __syncthreads();
    for (int o = 128; o > 0; o >>= 1) {
        if (threadIdx.x < o) sm[threadIdx.x] += sm[threadIdx.x + o];
        __syncthreads();
    }
    if (threadIdx.x == 0) dis[i] = rsqrtf(sm[0] + 2.0f);
}

__global__ void k_scale_rows(const float* __restrict__ HW, const float* __restrict__ dis,
                             float* __restrict__ HWs) {
    int i = blockIdx.x, c = threadIdx.x;
    HWs[i * HID + c] = dis[i] * HW[i * HID + c];
}

__global__ void k_gcn_epilogue(const float* __restrict__ T, const float* __restrict__ HW,
                               const float* __restrict__ dis, const float* __restrict__ b,
                               float* __restrict__ out, int relu) {
    int i = blockIdx.x, c = threadIdx.x;
    float di = dis[i];
    float v = di * (T[i * HID + c] + 2.0f * di * HW[i * HID + c]) + b[c];
    if (relu) v = fmaxf(v, 0.0f);
    out[i * HID + c] = v;
}

__global__ void k_pnorm(const float* __restrict__ p_pool, float* __restrict__ pn) {
    int r = blockIdx.x;
    float v = p_pool[r * HID + threadIdx.x];
    __shared__ float sm[HID];
    sm[threadIdx.x] = v * v;
    __syncthreads();
    for (int o = 64; o > 0; o >>= 1) {
        if (threadIdx.x < o) sm[threadIdx.x] += sm[threadIdx.x + o];
        __syncthreads();
    }
    if (threadIdx.x == 0) pn[r] = sqrtf(sm[0]);
}

__global__ void k_score(const float* __restrict__ h, const float* __restrict__ p,
                        const float* __restrict__ pn, int lvl, float* __restrict__ score) {
    int i = blockIdx.x;
    __shared__ float sm[HID];
    sm[threadIdx.x] = h[i * HID + threadIdx.x] * p[threadIdx.x];
    __syncthreads();
    for (int o = 64; o > 0; o >>= 1) {
        if (threadIdx.x < o) sm[threadIdx.x] += sm[threadIdx.x + o];
        __syncthreads();
    }
    if (threadIdx.x == 0) score[i] = sm[0] / pn[lvl];
}

// Single-block bitonic sort: descending by score, ties -> lower index first (jax.lax.top_k).
__global__ void k_topk_sort(const float* __restrict__ score, int n, int k,
                            int* __restrict__ perm, float* __restrict__ vals) {
    __shared__ float ss[4096];
    __shared__ int   si[4096];
    for (int i = threadIdx.x; i < n; i += blockDim.x) { ss[i] = score[i]; si[i] = i; }
    __syncthreads();
    for (int ksz = 2; ksz <= n; ksz <<= 1) {
        for (int j = ksz >> 1; j > 0; j >>= 1) {
            for (int idx = threadIdx.x; idx < n; idx += blockDim.x) {
                int ixj = idx ^ j;
                if (ixj > idx) {
                    float a = ss[idx], b = ss[ixj];
                    int ai = si[idx], bi = si[ixj];
                    bool beforeBA = (b > a) || (b == a && bi < ai);
                    bool beforeAB = (a > b) || (a == b && ai < bi);
                    bool sw = ((idx & ksz) == 0) ? beforeBA : beforeAB;
                    if (sw) { ss[idx] = b; ss[ixj] = a; si[idx] = bi; si[ixj] = ai; }
                }
            }
            __syncthreads();
        }
    }
    for (int r = threadIdx.x; r < k; r += blockDim.x) { perm[r] = si[r]; vals[r] = ss[r]; }
}

__global__ void k_pool(const float* __restrict__ h, const int* __restrict__ perm,
                       const float* __restrict__ vals, float* __restrict__ hp) {
    int r = blockIdx.x, c = threadIdx.x;
    hp[r * HID + c] = h[perm[r] * HID + c] * tanhf(vals[r]);
}

__global__ void k_copy128(const float* __restrict__ src, float* __restrict__ dst) {
    int i = blockIdx.x, c = threadIdx.x;
    dst[i * HID + c] = src[i * HID + c];
}

__global__ void k_scatter_add(const float* __restrict__ hs, const int* __restrict__ perm,
                              float* __restrict__ out) {
    int r = blockIdx.x, c = threadIdx.x;
    out[perm[r] * HID + c] += hs[r * HID + c];  // perm indices unique -> no atomics
}

// hw[i] = h[i,:] . Wout ; g[i] = dis[i]*hw[i]
__global__ void k_hw_out(const float* __restrict__ h, const float* __restrict__ Wout,
                         const float* __restrict__ dis, float* __restrict__ hw,
                         float* __restrict__ g) {
    int i = blockIdx.x;
    __shared__ float sm[HID];
    sm[threadIdx.x] = h[i * HID + threadIdx.x] * Wout[threadIdx.x];
    __syncthreads();
    for (int o = 64; o > 0; o >>= 1) {
        if (threadIdx.x < o) sm[threadIdx.x] += sm[threadIdx.x + o];
        __syncthreads();
    }
    if (threadIdx.x == 0) { hw[i] = sm[0]; g[i] = dis[i] * sm[0]; }
}

__global__ void k_final(const float* __restrict__ A, const float* __restrict__ g,
                        const float* __restrict__ hw, const float* __restrict__ dis,
                        const float* __restrict__ b, float* __restrict__ out, int n) {
    int i = blockIdx.x;
    float s = 0.0f;
    for (int j = threadIdx.x; j < n; j += blockDim.x) s += A[(size_t)i * n + j] * g[j];
    __shared__ float sm[256];
    sm[threadIdx.x] = s;
    __syncthreads();
    for (int o = 128; o > 0; o >>= 1) {
        if (threadIdx.x < o) sm[threadIdx.x] += sm[threadIdx.x + o];
        __syncthreads();
    }
    if (threadIdx.x == 0) {
        float di = dis[i];
        out[i] = di * (sm[0] + 2.0f * di * hw[i]) + b[0];
    }
}

// ---------------- host orchestration ----------------

static void gcn(const float* A, int n, const float* hin, const float* W, const float* b,
                float* hout, bool relu, float* T1, float* T2, float* T3, float* dis) {
    // T1 = hin @ W   (n x 128 x 128)
    dim3 g1((HID + 63) / 64, (n + 63) / 64);
    k_gemm<64, 64, 16, 4, 4><<<g1, 256>>>(hin, W, T1, n, HID, HID, 0);
    k_dis<<<n, 256>>>(A, dis, n);
    k_scale_rows<<<n, HID>>>(T1, dis, T2);
    // T3 = A @ T2   (n x 128, K = n)
    dim3 g2((HID + 63) / 64, (n + 63) / 64);
    k_gemm<64, 64, 16, 4, 4><<<g2, 256>>>(A, T2, T3, n, HID, n, 0);
    k_gcn_epilogue<<<n, HID>>>(T3, T1, dis, b, hout, relu ? 1 : 0);
}

extern "C" void kernel_launch(void* const* d_in, const int* in_sizes, int n_in,
                              void* d_out, int out_size) {
    const float* x      = (const float*)d_in[0];
    const int*   ei     = (const int*)d_in[1];
    // d_in[2] = batch (unused)
    const float* W_enc  = (const float*)d_in[3];
    const float* b_enc  = (const float*)d_in[4];
    const float* W_down = (const float*)d_in[5];
    const float* b_down = (const float*)d_in[6];
    const float* W_up   = (const float*)d_in[7];
    const float* b_up   = (const float*)d_in[8];
    const float* W_out  = (const float*)d_in[9];
    const float* b_out  = (const float*)d_in[10];
    const float* p_pool = (const float*)d_in[11];
    float* out = (float*)d_out;

    float *A0, *A1, *A2, *A3, *A4, *Pb, *Qb;
    float *X0, *X1, *X2, *X3, *Ha, *Hb, *T1, *T2, *T3;
    float *Dis, *Score, *Vals, *HWo, *Gv, *Pn;
    int *P0, *P1, *P2, *P3;
    cudaGetSymbolAddress((void**)&A0, dA0);
    cudaGetSymbolAddress((void**)&A1, dA1);
    cudaGetSymbolAddress((void**)&A2, dA2);
    cudaGetSymbolAddress((void**)&A3, dA3);
    cudaGetSymbolAddress((void**)&A4, dA4);
    cudaGetSymbolAddress((void**)&Pb, dPbuf);
    cudaGetSymbolAddress((void**)&Qb, dQbuf);
    cudaGetSymbolAddress((void**)&X0, dX0);
    cudaGetSymbolAddress((void**)&X1, dX1);
    cudaGetSymbolAddress((void**)&X2, dX2);
    cudaGetSymbolAddress((void**)&X3, dX3);
    cudaGetSymbolAddress((void**)&Ha, dHa);
    cudaGetSymbolAddress((void**)&Hb, dHb);
    cudaGetSymbolAddress((void**)&T1, dT1);
    cudaGetSymbolAddress((void**)&T2, dT2);
    cudaGetSymbolAddress((void**)&T3, dT3);
    cudaGetSymbolAddress((void**)&Dis, dDis);
    cudaGetSymbolAddress((void**)&Score, dScore);
    cudaGetSymbolAddress((void**)&Vals, dVals);
    cudaGetSymbolAddress((void**)&HWo, dHWo);
    cudaGetSymbolAddress((void**)&Gv, dGv);
    cudaGetSymbolAddress((void**)&Pn, dPn);
    cudaGetSymbolAddress((void**)&P0, dPerm0);
    cudaGetSymbolAddress((void**)&P1, dPerm1);
    cudaGetSymbolAddress((void**)&P2, dPerm2);
    cudaGetSymbolAddress((void**)&P3, dPerm3);

    const int ns[5] = {4096, 2048, 1024, 512, 256};
    float* As[5] = {A0, A1, A2, A3, A4};
    float* Xs[4] = {X0, X1, X2, X3};
    int*   Ps[4] = {P0, P1, P2, P3};

    // 1) node encoder: Ha = x @ W_enc + b_enc
    k_encoder<<<N0, HID>>>(x, W_enc, b_enc, Ha);

    // 2) dense adjacency A0[dst, src] += 1
    k_zero<<<4096, 256>>>(A0, (size_t)N0 * N0);
    k_build_adj<<<EDGES / 256, 256>>>(ei, A0);

    // 3) pool vector norms
    k_pnorm<<<4, HID>>>(p_pool, Pn);

    // 4) down conv 0 -> X0
    gcn(A0, N0, Ha, W_down, b_down, X0, true, T1, T2, T3, Dis);

    // 5) down path with pooled-submatrix augment
    const float* hprev = X0;
    for (int i = 1; i <= 4; i++) {
        int n = ns[i - 1], k = ns[i];
        k_score<<<n, HID>>>(hprev, p_pool + (size_t)(i - 1) * HID, Pn, i - 1, Score);
        k_topk_sort<<<1, 1024>>>(Score, n, k, Ps[i - 1], Vals);
        k_pool<<<k, HID>>>(hprev, Ps[i - 1], Vals, Ha);

        size_t t = (size_t)k * n;
        k_gather_rows<<<(unsigned)((t + 255) / 256), 256>>>(As[i - 1], Ps[i - 1], Pb, k, n);
        k_gather_cols<<<(unsigned)((t + 255) / 256), 256>>>(As[i - 1], Ps[i - 1], Qb, k, n);
        dim3 gg((k + 127) / 128, (k + 127) / 128);
        k_gemm<128, 128, 8, 8, 8><<<gg, 256>>>(Pb, Qb, As[i], k, k, n, 1);

        float* hout = (i < 4) ? Xs[i] : Hb;
        gcn(As[i], k, Ha, W_down + (size_t)i * HID * HID, b_down + (size_t)i * HID,
            hout, true, T1, T2, T3, Dis);
        hprev = hout;
    }

    // 6) up path
    float* hcur = Hb;  // bottom features (256 x 128)
    for (int i = 0; i < 4; i++) {
        int j = 3 - i;
        int n = ns[j], k = ns[j + 1];
        k_copy128<<<n, HID>>>(Xs[j], Ha);
        k_scatter_add<<<k, HID>>>(hcur, Ps[j], Ha);
        if (i < 3) {
            gcn(As[j], n, Ha, W_up + (size_t)i * HID * HID, b_up + (size_t)i * HID,
                Hb, true, T1, T2, T3, Dis);
            hcur = Hb;
        } else {
            // final GCN conv with W_out (HID -> 1), no activation, on A0
            k_dis<<<n, 256>>>(As[0], Dis, n);
            k_hw_out<<<n, HID>>>(Ha, W_out, Dis, HWo, Gv);
            k_final<<<n, 256>>>(As[0], Gv, HWo, Dis, b_out, out, n);
        }
    }
}

// round 2
// speedup vs baseline: 2.6265x; 2.6265x over previous
#include <cuda_runtime.h>
#include <math.h>
#include <stdint.h>

#define N0    4096
#define EDGES 65536
#define HID   128

// ---------------- device global scratch (no allocations allowed) ----------------
__device__ float dA1[(size_t)2048 * 2048];     // 16 MB
__device__ float dA2[(size_t)1024 * 1024];     // 4 MB
__device__ float dA3[(size_t)512 * 512];
__device__ float dA4[(size_t)256 * 256];
__device__ float dPbuf[(size_t)1024 * 2048];   // gathered rows  B[perm,:]  (k x n), max level-2
__device__ float dQbuf[(size_t)2048 * 1024];   // gathered cols  B[:,perm]  (n x k)
__device__ float dX0[N0 * HID];
__device__ float dX1[2048 * HID];
__device__ float dX2[1024 * HID];
__device__ float dX3[512 * HID];
__device__ float dHa[N0 * HID];
__device__ float dHb[N0 * HID];
__device__ float dT1[N0 * HID];   // h@W
__device__ float dT2[N0 * HID];   // dis * (h@W)
__device__ float dT3[N0 * HID];   // A @ T2
__device__ float dDis[N0];
__device__ float dScore[N0];
__device__ float dVals[N0];
__device__ float dHWo[N0];
__device__ float dGv[N0];
__device__ int   dPerm0[2048];
__device__ int   dPerm1[1024];
__device__ int   dPerm2[512];
__device__ int   dPerm3[256];
__device__ int   dInv[N0];
__device__ float dPn[4];
// CSR of A0 (all edges, duplicates kept as separate unit-valued entries)
__device__ int   dRp[N0 + 1];
__device__ int   dColA[EDGES];
__device__ int   dCnt[N0];
__device__ int   dCur[N0];

// ---------------- kernels ----------------

__global__ void k_zero_int(int* p, int n) {
    int i = blockIdx.x * blockDim.x + threadIdx.x;
    if (i < n) p[i] = 0;
}

__global__ void k_count(const int* __restrict__ ei, int* __restrict__ cnt) {
    int e = blockIdx.x * blockDim.x + threadIdx.x;
    if (e < EDGES) atomicAdd(&cnt[ei[EDGES + e]], 1);
}

// exclusive scan of 4096 ints, single block of 1024 threads
__global__ void k_scan(const int* __restrict__ cnt, int* __restrict__ rp) {
    __shared__ int buf[N0];
    int tid = threadIdx.x;
    for (int i = tid; i < N0; i += 1024) buf[i] = cnt[i];
    __syncthreads();
    for (int off = 1; off < N0; off <<= 1) {
        int v[4];
#pragma unroll
        for (int j = 0; j < 4; j++) {
            int i = tid + j * 1024;
            v[j] = (i >= off) ? buf[i - off] : 0;
        }
        __syncthreads();
#pragma unroll
        for (int j = 0; j < 4; j++) buf[tid + j * 1024] += v[j];
        __syncthreads();
    }
    if (tid == 0) rp[0] = 0;
    for (int i = tid; i < N0; i += 1024) rp[i + 1] = buf[i];
}

__global__ void k_fill(const int* __restrict__ ei, const int* __restrict__ rp,
                       int* __restrict__ cur, int* __restrict__ colA) {
    int e = blockIdx.x * blockDim.x + threadIdx.x;
    if (e < EDGES) {
        int s = ei[e], d = ei[EDGES + e];
        int pos = rp[d] + atomicAdd(&cur[d], 1);
        colA[pos] = s;
    }
}

__global__ void k_dis0(const int* __restrict__ cnt, float* __restrict__ dis) {
    int i = blockIdx.x * blockDim.x + threadIdx.x;
    if (i < N0) dis[i] = rsqrtf((float)cnt[i] + 2.0f);
}

// T3[i,:] = sum over CSR row i of T2[col,:]
__global__ void k_spmm(const int* __restrict__ rp, const int* __restrict__ colA,
                       const float* __restrict__ T2, float* __restrict__ T3) {
    int i = blockIdx.x, c = threadIdx.x;
    int s = rp[i], e = rp[i + 1];
    float acc = 0.0f;
    for (int t = s; t < e; t++) acc += T2[colA[t] * HID + c];
    T3[i * HID + c] = acc;
}

__global__ void k_set_neg1(int* __restrict__ inv, int n) {
    int i = blockIdx.x * blockDim.x + threadIdx.x;
    if (i < n) inv[i] = -1;
}

__global__ void k_set_inv(const int* __restrict__ perm, int* __restrict__ inv, int k) {
    int i = blockIdx.x * blockDim.x + threadIdx.x;
    if (i < k) inv[perm[i]] = i;
}

// Level-1 augment via SpGEMM: A1[r,c] = (B@B)[perm[r], perm[c]], diag zeroed.
// B = offdiag(A0) + I, CSR entries valued 1 (duplicates are separate entries).
__global__ void k_spgemm(const int* __restrict__ rp, const int* __restrict__ colA,
                         const int* __restrict__ perm, const int* __restrict__ inv,
                         float* __restrict__ Aout, int kOut) {
    __shared__ float accs[2048];
    int r = blockIdx.x;
    int pr = perm[r];
    for (int i = threadIdx.x; i < kOut; i += blockDim.x) accs[i] = 0.0f;
    __syncthreads();
    int s = rp[pr], e = rp[pr + 1];
    int outerCnt = (e - s) + 1;  // row entries + implicit diag (m = pr)
    for (int oi = threadIdx.x; oi < outerCnt; oi += blockDim.x) {
        int m = (oi < e - s) ? colA[s + oi] : pr;
        if (oi < e - s && m == pr) continue;  // offdiag(A): skip self entries
        int s2 = rp[m], e2 = rp[m + 1];
        for (int t = s2; t < e2; t++) {
            int j = colA[t];
            if (j == m) continue;             // offdiag of inner row
            int c = inv[j];
            if (c >= 0) atomicAdd(&accs[c], 1.0f);
        }
        int cm = inv[m];                       // implicit diag B[m,m] = 1
        if (cm >= 0) atomicAdd(&accs[cm], 1.0f);
    }
    __syncthreads();
    for (int c = threadIdx.x; c < kOut; c += blockDim.x)
        Aout[(size_t)r * kOut + c] = (c == r) ? 0.0f : accs[c];
}

__global__ void k_encoder(const float* __restrict__ x, const float* __restrict__ W,
                          const float* __restrict__ b, float* __restrict__ h) {
    int i = blockIdx.x;
    int c = threadIdx.x;
    float acc = b[c];
#pragma unroll
    for (int k = 0; k < 16; k++) acc += x[i * 16 + k] * W[k * HID + c];
    h[i * HID + c] = acc;
}

// Generic register-blocked SGEMM: C[M,N] = A[M,K] @ B[K,N], row-major.
template <int BM, int BN, int BK, int TM, int TN>
__global__ void k_gemm(const float* __restrict__ A, const float* __restrict__ B,
                       float* __restrict__ C, int M, int N, int K, int zeroDiag) {
    __shared__ float As[BK][BM];
    __shared__ float Bs[BK][BN];
    const int NT = (BM / TM) * (BN / TN);
    int tid = threadIdx.x;
    int m0 = blockIdx.y * BM, n0 = blockIdx.x * BN;
    int tm = (tid / (BN / TN)) * TM;
    int tn = (tid % (BN / TN)) * TN;
    float acc[TM][TN];
#pragma unroll
    for (int a = 0; a < TM; a++)
#pragma unroll
        for (int b = 0; b < TN; b++) acc[a][b] = 0.0f;

    for (int k0 = 0; k0 < K; k0 += BK) {
        for (int i = tid; i < BM * BK; i += NT) {
            int mm = i / BK, kk = i % BK;
            int gm = m0 + mm, gk = k0 + kk;
            As[kk][mm] = (gm < M && gk < K) ? A[(size_t)gm * K + gk] : 0.0f;
        }
        for (int i = tid; i < BK * BN; i += NT) {
            int kk = i / BN, nn = i % BN;
            int gk = k0 + kk, gn = n0 + nn;
            Bs[kk][nn] = (gk < K && gn < N) ? B[(size_t)gk * N + gn] : 0.0f;
        }
        __syncthreads();
#pragma unroll
        for (int kk = 0; kk < BK; kk++) {
            float ar[TM], br[TN];
#pragma unroll
            for (int a = 0; a < TM; a++) ar[a] = As[kk][tm + a];
#pragma unroll
            for (int b = 0; b < TN; b++) br[b] = Bs[kk][tn + b];
#pragma unroll
            for (int a = 0; a < TM; a++)
#pragma unroll
                for (int b = 0; b < TN; b++) acc[a][b] += ar[a] * br[b];
        }
        __syncthreads();
    }
#pragma unroll
    for (int a = 0; a < TM; a++)
#pragma unroll
        for (int b = 0; b < TN; b++) {
            int gm = m0 + tm + a, gn = n0 + tn + b;
            if (gm < M && gn < N) {
                float v = acc[a][b];
                if (zeroDiag && gm == gn) v = 0.0f;
                C[(size_t)gm * N + gn] = v;
            }
        }
}

// P[r, m] = B[perm[r], m] where B = offdiag(A) + I (dense A)
__global__ void k_gather_rows(const float* __restrict__ A, const int* __restrict__ perm,
                              float* __restrict__ P, int k, int n) {
    size_t idx = (size_t)blockIdx.x * blockDim.x + threadIdx.x;
    if (idx < (size_t)k * n) {
        int r = (int)(idx / n), m = (int)(idx % n);
        int pr = perm[r];
        float v = A[(size_t)pr * n + m];
        P[idx] = (m == pr) ? 1.0f : v;
    }
}

// Q[m, c] = B[m, perm[c]] where B = offdiag(A) + I (dense A)
__global__ void k_gather_cols(const float* __restrict__ A, const int* __restrict__ perm,
                              float* __restrict__ Q, int k, int n) {
    size_t idx = (size_t)blockIdx.x * blockDim.x + threadIdx.x;
    if (idx < (size_t)n * k) {
        int m = (int)(idx / k), c = (int)(idx % k);
        int pc = perm[c];
        float v = A[(size_t)m * n + pc];
        Q[idx] = (m == pc) ? 1.0f : v;
    }
}

// dis[i] = rsqrt(rowsum(A[i,:]) + 2)  (dense A)
__global__ void k_dis(const float* __restrict__ A, float* __restrict__ dis, int n) {
    int i = blockIdx.x;
    float s = 0.0f;
    for (int j = threadIdx.x; j < n; j += blockDim.x) s += A[(size_t)i * n + j];
    __shared__ float sm[256];
    sm[threadIdx.x] = s;
    __syncthreads();
    for (int o = 128; o > 0; o >>= 1) {
        if (threadIdx.x < o) sm[threadIdx.x] += sm[threadIdx.x + o];
        __syncthreads();
    }
    if (threadIdx.x == 0) dis[i] = rsqrtf(sm[0] + 2.0f);
}

__global__ void k_scale_rows(const float* __restrict__ HW, const float* __restrict__ dis,
                             float* __restrict__ HWs) {
    int i = blockIdx.x, c = threadIdx.x;
    HWs[i * HID + c] = dis[i] * HW[i * HID + c];
}

__global__ void k_gcn_epilogue(const float* __restrict__ T, const float* __restrict__ HW,
                               const float* __restrict__ dis, const float* __restrict__ b,
                               float* __restrict__ out, int relu) {
    int i = blockIdx.x, c = threadIdx.x;
    float di = dis[i];
    float v = di * (T[i * HID + c] + 2.0f * di * HW[i * HID + c]) + b[c];
    if (relu) v = fmaxf(v, 0.0f);
    out[i * HID + c] = v;
}

__global__ void k_pnorm(const float* __restrict__ p_pool, float* __restrict__ pn) {
    int r = blockIdx.x;
    float v = p_pool[r * HID + threadIdx.x];
    __shared__ float sm[HID];
    sm[threadIdx.x] = v * v;
    __syncthreads();
    for (int o = 64; o > 0; o >>= 1) {
        if (threadIdx.x < o) sm[threadIdx.x] += sm[threadIdx.x + o];
        __syncthreads();
    }
    if (threadIdx.x == 0) pn[r] = sqrtf(sm[0]);
}

__global__ void k_score(const float* __restrict__ h, const float* __restrict__ p,
                        const float* __restrict__ pn, int lvl, float* __restrict__ score) {
    int i = blockIdx.x;
    __shared__ float sm[HID];
    sm[threadIdx.x] = h[i * HID + threadIdx.x] * p[threadIdx.x];
    __syncthreads();
    for (int o = 64; o > 0; o >>= 1) {
        if (threadIdx.x < o) sm[threadIdx.x] += sm[threadIdx.x + o];
        __syncthreads();
    }
    if (threadIdx.x == 0) score[i] = sm[0] / pn[lvl];
}

// Single-block bitonic sort: descending by score, ties -> lower index first.
__global__ void k_topk_sort(const float* __restrict__ score, int n, int k,
                            int* __restrict__ perm, float* __restrict__ vals) {
    __shared__ float ss[4096];
    __shared__ int   si[4096];
    for (int i = threadIdx.x; i < n; i += blockDim.x) { ss[i] = score[i]; si[i] = i; }
    __syncthreads();
    for (int ksz = 2; ksz <= n; ksz <<= 1) {
        for (int j = ksz >> 1; j > 0; j >>= 1) {
            for (int idx = threadIdx.x; idx < n; idx += blockDim.x) {
                int ixj = idx ^ j;
                if (ixj > idx) {
                    float a = ss[idx], b = ss[ixj];
                    int ai = si[idx], bi = si[ixj];
                    bool beforeBA = (b > a) || (b == a && bi < ai);
                    bool beforeAB = (a > b) || (a == b && ai < bi);
                    bool sw = ((idx & ksz) == 0) ? beforeBA : beforeAB;
                    if (sw) { ss[idx] = b; ss[ixj] = a; si[idx] = bi; si[ixj] = ai; }
                }
            }
            __syncthreads();
        }
    }
    for (int r = threadIdx.x; r < k; r += blockDim.x) { perm[r] = si[r]; vals[r] = ss[r]; }
}

__global__ void k_pool(const float* __restrict__ h, const int* __restrict__ perm,
                       const float* __restrict__ vals, float* __restrict__ hp) {
    int r = blockIdx.x, c = threadIdx.x;
    hp[r * HID + c] = h[perm[r] * HID + c] * tanhf(vals[r]);
}

__global__ void k_copy128(const float* __restrict__ src, float* __restrict__ dst) {
    int i = blockIdx.x, c = threadIdx.x;
    dst[i * HID + c] = src[i * HID + c];
}

__global__ void k_scatter_add(const float* __restrict__ hs, const int* __restrict__ perm,
                              float* __restrict__ out) {
    int r = blockIdx.x, c = threadIdx.x;
    out[perm[r] * HID + c] += hs[r * HID + c];  // perm indices unique -> no atomics
}

// hw[i] = h[i,:] . Wout ; g[i] = dis[i]*hw[i]
__global__ void k_hw_out(const float* __restrict__ h, const float* __restrict__ Wout,
                         const float* __restrict__ dis, float* __restrict__ hw,
                         float* __restrict__ g) {
    int i = blockIdx.x;
    __shared__ float sm[HID];
    sm[threadIdx.x] = h[i * HID + threadIdx.x] * Wout[threadIdx.x];
    __syncthreads();
    for (int o = 64; o > 0; o >>= 1) {
        if (threadIdx.x < o) sm[threadIdx.x] += sm[threadIdx.x + o];
        __syncthreads();
    }
    if (threadIdx.x == 0) { hw[i] = sm[0]; g[i] = dis[i] * sm[0]; }
}

// final conv on CSR(A0): out[i] = dis[i]*(sum_{e in row i} g[col] + 2*dis[i]*hw[i]) + b0
__global__ void k_final_sp(const int* __restrict__ rp, const int* __restrict__ colA,
                           const float* __restrict__ g, const float* __restrict__ hw,
                           const float* __restrict__ dis, const float* __restrict__ b,
                           float* __restrict__ out) {
    int i = blockIdx.x * blockDim.x + threadIdx.x;
    if (i < N0) {
        float s = 0.0f;
        int a = rp[i], e = rp[i + 1];
        for (int t = a; t < e; t++) s += g[colA[t]];
        float di = dis[i];
        out[i] = di * (s + 2.0f * di * hw[i]) + b[0];
    }
}

// ---------------- host orchestration ----------------

static void gcn_dense(const float* A, int n, const float* hin, const float* W, const float* b,
                      float* hout, bool relu, float* T1, float* T2, float* T3, float* dis) {
    dim3 g1((HID + 63) / 64, (n + 63) / 64);
    k_gemm<64, 64, 16, 4, 4><<<g1, 256>>>(hin, W, T1, n, HID, HID, 0);
    k_dis<<<n, 256>>>(A, dis, n);
    k_scale_rows<<<n, HID>>>(T1, dis, T2);
    k_gemm<64, 64, 16, 4, 4><<<g1, 256>>>(A, T2, T3, n, HID, n, 0);
    k_gcn_epilogue<<<n, HID>>>(T3, T1, dis, b, hout, relu ? 1 : 0);
}

extern "C" void kernel_launch(void* const* d_in, const int* in_sizes, int n_in,
                              void* d_out, int out_size) {
    const float* x      = (const float*)d_in[0];
    const int*   ei     = (const int*)d_in[1];
    const float* W_enc  = (const float*)d_in[3];
    const float* b_enc  = (const float*)d_in[4];
    const float* W_down = (const float*)d_in[5];
    const float* b_down = (const float*)d_in[6];
    const float* W_up   = (const float*)d_in[7];
    const float* b_up   = (const float*)d_in[8];
    const float* W_out  = (const float*)d_in[9];
    const float* b_out  = (const float*)d_in[10];
    const float* p_pool = (const float*)d_in[11];
    float* out = (float*)d_out;

    float *A1, *A2, *A3, *A4, *Pb, *Qb;
    float *X0, *X1, *X2, *X3, *Ha, *Hb, *T1, *T2, *T3;
    float *Dis, *Score, *Vals, *HWo, *Gv, *Pn;
    int *P0, *P1, *P2, *P3, *Inv, *Rp, *ColA, *Cnt, *Cur;
    cudaGetSymbolAddress((void**)&A1, dA1);
    cudaGetSymbolAddress((void**)&A2, dA2);
    cudaGetSymbolAddress((void**)&A3, dA3);
    cudaGetSymbolAddress((void**)&A4, dA4);
    cudaGetSymbolAddress((void**)&Pb, dPbuf);
    cudaGetSymbolAddress((void**)&Qb, dQbuf);
    cudaGetSymbolAddress((void**)&X0, dX0);
    cudaGetSymbolAddress((void**)&X1, dX1);
    cudaGetSymbolAddress((void**)&X2, dX2);
    cudaGetSymbolAddress((void**)&X3, dX3);
    cudaGetSymbolAddress((void**)&Ha, dHa);
    cudaGetSymbolAddress((void**)&Hb, dHb);
    cudaGetSymbolAddress((void**)&T1, dT1);
    cudaGetSymbolAddress((void**)&T2, dT2);
    cudaGetSymbolAddress((void**)&T3, dT3);
    cudaGetSymbolAddress((void**)&Dis, dDis);
    cudaGetSymbolAddress((void**)&Score, dScore);
    cudaGetSymbolAddress((void**)&Vals, dVals);
    cudaGetSymbolAddress((void**)&HWo, dHWo);
    cudaGetSymbolAddress((void**)&Gv, dGv);
    cudaGetSymbolAddress((void**)&Pn, dPn);
    cudaGetSymbolAddress((void**)&P0, dPerm0);
    cudaGetSymbolAddress((void**)&P1, dPerm1);
    cudaGetSymbolAddress((void**)&P2, dPerm2);
    cudaGetSymbolAddress((void**)&P3, dPerm3);
    cudaGetSymbolAddress((void**)&Inv, dInv);
    cudaGetSymbolAddress((void**)&Rp, dRp);
    cudaGetSymbolAddress((void**)&ColA, dColA);
    cudaGetSymbolAddress((void**)&Cnt, dCnt);
    cudaGetSymbolAddress((void**)&Cur, dCur);

    const int ns[5] = {4096, 2048, 1024, 512, 256};
    float* As[5] = {nullptr, A1, A2, A3, A4};
    float* Xs[4] = {X0, X1, X2, X3};
    int*   Ps[4] = {P0, P1, P2, P3};

    // 1) node encoder
    k_encoder<<<N0, HID>>>(x, W_enc, b_enc, Ha);

    // 2) CSR of A0
    k_zero_int<<<N0 / 256, 256>>>(Cnt, N0);
    k_zero_int<<<N0 / 256, 256>>>(Cur, N0);
    k_count<<<EDGES / 256, 256>>>(ei, Cnt);
    k_scan<<<1, 1024>>>(Cnt, Rp);
    k_fill<<<EDGES / 256, 256>>>(ei, Rp, Cur, ColA);
    k_dis0<<<N0 / 256, 256>>>(Cnt, Dis);

    // 3) pool vector norms
    k_pnorm<<<4, HID>>>(p_pool, Pn);

    // 4) down conv 0 (sparse propagation) -> X0
    {
        dim3 g1((HID + 63) / 64, (N0 + 63) / 64);
        k_gemm<64, 64, 16, 4, 4><<<g1, 256>>>(Ha, W_down, T1, N0, HID, HID, 0);
        k_scale_rows<<<N0, HID>>>(T1, Dis, T2);
        k_spmm<<<N0, HID>>>(Rp, ColA, T2, T3);
        k_gcn_epilogue<<<N0, HID>>>(T3, T1, Dis, b_down, X0, 1);
    }

    // 5) down path
    const float* hprev = X0;
    for (int i = 1; i <= 4; i++) {
        int n = ns[i - 1], k = ns[i];
        k_score<<<n, HID>>>(hprev, p_pool + (size_t)(i - 1) * HID, Pn, i - 1, Score);
        k_topk_sort<<<1, 1024>>>(Score, n, k, Ps[i - 1], Vals);
        k_pool<<<k, HID>>>(hprev, Ps[i - 1], Vals, Ha);

        if (i == 1) {
            // sparse augment from CSR(A0)
            k_set_neg1<<<(n + 255) / 256, 256>>>(Inv, n);
            k_set_inv<<<(k + 255) / 256, 256>>>(Ps[0], Inv, k);
            k_spgemm<<<k, 256>>>(Rp, ColA, Ps[0], Inv, A1, k);
        } else {
            size_t t = (size_t)k * n;
            k_gather_rows<<<(unsigned)((t + 255) / 256), 256>>>(As[i - 1], Ps[i - 1], Pb, k, n);
            k_gather_cols<<<(unsigned)((t + 255) / 256), 256>>>(As[i - 1], Ps[i - 1], Qb, k, n);
            dim3 gg((k + 63) / 64, (k + 63) / 64);
            k_gemm<64, 64, 16, 4, 4><<<gg, 256>>>(Pb, Qb, As[i], k, k, n, 1);
        }

        float* hout = (i < 4) ? Xs[i] : Hb;
        gcn_dense(As[i], k, Ha, W_down + (size_t)i * HID * HID, b_down + (size_t)i * HID,
                  hout, true, T1, T2, T3, Dis);
        hprev = hout;
    }

    // 6) up path
    float* hcur = Hb;
    for (int i = 0; i < 4; i++) {
        int j = 3 - i;
        int n = ns[j], k = ns[j + 1];
        k_copy128<<<n, HID>>>(Xs[j], Ha);
        k_scatter_add<<<k, HID>>>(hcur, Ps[j], Ha);
        if (i < 3) {
            gcn_dense(As[j], n, Ha, W_up + (size_t)i * HID * HID, b_up + (size_t)i * HID,
                      Hb, true, T1, T2, T3, Dis);
            hcur = Hb;
        } else {
            // final GCN conv (HID -> 1) on sparse A0
            k_dis0<<<N0 / 256, 256>>>(Cnt, Dis);
            k_hw_out<<<n, HID>>>(Ha, W_out, Dis, HWo, Gv);
            k_final_sp<<<(n + 127) / 128, 128>>>(Rp, ColA, Gv, HWo, Dis, b_out, out);
        }
    }
}

// round 3
// speedup vs baseline: 5.0818x; 1.9348x over previous
#include <cuda_runtime.h>
#include <math.h>
#include <stdint.h>

#define N0    4096
#define EDGES 65536
#define HID   128

// ---------------- device global scratch ----------------
// sparse A1 (level-1 adjacency), row stride 2048
__device__ int   dA1cols[(size_t)2048 * 2048];   // 16 MB
__device__ float dA1vals[(size_t)2048 * 2048];   // 16 MB
__device__ int   dA1cnt[2048];
__device__ float dA1rsum[2048];
// dense adjacencies for levels 2..4
__device__ float dA2[(size_t)1024 * 1024];       // 4 MB
__device__ float dA3[(size_t)512 * 512];
__device__ float dA4[(size_t)256 * 256];
__device__ float dPbuf[(size_t)512 * 1024];      // gathered rows (max: level-3)
__device__ float dQbuf[(size_t)1024 * 512];      // gathered cols
__device__ float dX0[N0 * HID];
__device__ float dX1[2048 * HID];
__device__ float dX2[1024 * HID];
__device__ float dX3[512 * HID];
__device__ float dHa[N0 * HID];
__device__ float dHb[N0 * HID];
__device__ float dT1[N0 * HID];
__device__ float dT2[N0 * HID];
__device__ float dDis[N0];
__device__ float dScore[N0];
__device__ float dVals[N0];
__device__ float dHWo[N0];
__device__ float dGv[N0];
__device__ int   dPerm0[2048];
__device__ int   dPerm1[1024];
__device__ int   dPerm2[512];
__device__ int   dPerm3[256];
__device__ int   dInv[N0];
__device__ float dPn[4];
// CSR of A0 (duplicates kept as separate unit entries)
__device__ int   dRp[N0 + 1];
__device__ int   dColA[EDGES];
__device__ int   dCnt[N0];
__device__ int   dCur[N0];

// ---------------- setup kernels ----------------

__global__ void k_zero_int(int* p, int n) {
    int i = blockIdx.x * blockDim.x + threadIdx.x;
    if (i < n) p[i] = 0;
}

__global__ void k_count(const int* __restrict__ ei, int* __restrict__ cnt) {
    int e = blockIdx.x * blockDim.x + threadIdx.x;
    if (e < EDGES) atomicAdd(&cnt[ei[EDGES + e]], 1);
}

__global__ void k_scan(const int* __restrict__ cnt, int* __restrict__ rp) {
    __shared__ int buf[N0];
    int tid = threadIdx.x;
    for (int i = tid; i < N0; i += 1024) buf[i] = cnt[i];
    __syncthreads();
    for (int off = 1; off < N0; off <<= 1) {
        int v[4];
#pragma unroll
        for (int j = 0; j < 4; j++) {
            int i = tid + j * 1024;
            v[j] = (i >= off) ? buf[i - off] : 0;
        }
        __syncthreads();
#pragma unroll
        for (int j = 0; j < 4; j++) buf[tid + j * 1024] += v[j];
        __syncthreads();
    }
    if (tid == 0) rp[0] = 0;
    for (int i = tid; i < N0; i += 1024) rp[i + 1] = buf[i];
}

__global__ void k_fill(const int* __restrict__ ei, const int* __restrict__ rp,
                       int* __restrict__ cur, int* __restrict__ colA) {
    int e = blockIdx.x * blockDim.x + threadIdx.x;
    if (e < EDGES) {
        int s = ei[e], d = ei[EDGES + e];
        int pos = rp[d] + atomicAdd(&cur[d], 1);
        colA[pos] = s;
    }
}

__global__ void k_dis0(const int* __restrict__ cnt, float* __restrict__ dis) {
    int i = blockIdx.x * blockDim.x + threadIdx.x;
    if (i < N0) dis[i] = rsqrtf((float)cnt[i] + 2.0f);
}

__global__ void k_dis_rsum(const float* __restrict__ rsum, float* __restrict__ dis, int n) {
    int i = blockIdx.x * blockDim.x + threadIdx.x;
    if (i < n) dis[i] = rsqrtf(rsum[i] + 2.0f);
}

__global__ void k_set_neg1(int* __restrict__ inv, int n) {
    int i = blockIdx.x * blockDim.x + threadIdx.x;
    if (i < n) inv[i] = -1;
}

__global__ void k_set_inv(const int* __restrict__ perm, int* __restrict__ inv, int k) {
    int i = blockIdx.x * blockDim.x + threadIdx.x;
    if (i < k) inv[perm[i]] = i;
}

// ---------------- sparse augment kernels ----------------

// Level-1 augment: A1 = offdiag((B@B)[perm,perm]) stored sparse.
// B = offdiag(A0) + I with unit-valued CSR entries (duplicates separate).
// Deterministic compaction via block scan.
__global__ void k_spgemm1(const int* __restrict__ rp, const int* __restrict__ colA,
                          const int* __restrict__ perm, const int* __restrict__ inv,
                          int* __restrict__ oCols, float* __restrict__ oVals,
                          int* __restrict__ oCnt, float* __restrict__ oRsum) {
    __shared__ float accs[2048];
    __shared__ int   tpre[256];
    __shared__ float fsum[256];
    int r = blockIdx.x;
    int pr = perm[r];
    for (int i = threadIdx.x; i < 2048; i += blockDim.x) accs[i] = 0.0f;
    __syncthreads();
    int s = rp[pr], e = rp[pr + 1];
    int outerCnt = (e - s) + 1;  // row entries + implicit diag (m = pr)
    for (int oi = threadIdx.x; oi < outerCnt; oi += blockDim.x) {
        int m = (oi < e - s) ? colA[s + oi] : pr;
        if (oi < e - s && m == pr) continue;
        int s2 = rp[m], e2 = rp[m + 1];
        for (int t = s2; t < e2; t++) {
            int j = colA[t];
            if (j == m) continue;
            int c = inv[j];
            if (c >= 0) atomicAdd(&accs[c], 1.0f);
        }
        int cm = inv[m];
        if (cm >= 0) atomicAdd(&accs[cm], 1.0f);
    }
    __syncthreads();
    // per-thread chunk of 8 columns -> counts -> inclusive scan -> ordered write
    int base = threadIdx.x * 8;
    int lc = 0;
    float ls = 0.0f;
#pragma unroll
    for (int j = 0; j < 8; j++) {
        int c = base + j;
        float v = accs[c];
        if (c != r && v != 0.0f) { lc++; ls += v; }
    }
    tpre[threadIdx.x] = lc;
    fsum[threadIdx.x] = ls;
    __syncthreads();
    for (int off = 1; off < 256; off <<= 1) {
        int v = (threadIdx.x >= off) ? tpre[threadIdx.x - off] : 0;
        float f = (threadIdx.x >= off) ? fsum[threadIdx.x - off] : 0.0f;
        __syncthreads();
        tpre[threadIdx.x] += v;
        fsum[threadIdx.x] += f;
        __syncthreads();
    }
    int pos = tpre[threadIdx.x] - lc;
#pragma unroll
    for (int j = 0; j < 8; j++) {
        int c = base + j;
        float v = accs[c];
        if (c != r && v != 0.0f) {
            oCols[(size_t)r * 2048 + pos] = c;
            oVals[(size_t)r * 2048 + pos] = v;
            pos++;
        }
    }
    if (threadIdx.x == 255) { oCnt[r] = tpre[255]; oRsum[r] = fsum[255]; }
}

// Level-2 augment: A2 (dense) = offdiag((B1@B1)[perm,perm]),
// B1 = A1(sparse, diag-free) + I.
__global__ void k_spgemm2(const int* __restrict__ oCols, const float* __restrict__ oVals,
                          const int* __restrict__ oCnt,
                          const int* __restrict__ perm, const int* __restrict__ inv,
                          float* __restrict__ A2, int kOut) {
    __shared__ float accs[1024];
    int r = blockIdx.x;
    int pr = perm[r];
    for (int i = threadIdx.x; i < kOut; i += blockDim.x) accs[i] = 0.0f;
    __syncthreads();
    int cnt = oCnt[pr];
    const int*   cols = oCols + (size_t)pr * 2048;
    const float* vals = oVals + (size_t)pr * 2048;
    int outerCnt = cnt + 1;
    for (int oi = threadIdx.x; oi < outerCnt; oi += blockDim.x) {
        int m; float vOut;
        if (oi < cnt) { m = cols[oi]; vOut = vals[oi]; }
        else          { m = pr;       vOut = 1.0f; }
        int cnt2 = oCnt[m];
        const int*   cols2 = oCols + (size_t)m * 2048;
        const float* vals2 = oVals + (size_t)m * 2048;
        for (int t = 0; t < cnt2; t++) {
            int c = inv[cols2[t]];
            if (c >= 0) atomicAdd(&accs[c], vOut * vals2[t]);
        }
        int cm = inv[m];  // implicit inner diag (m, 1)
        if (cm >= 0) atomicAdd(&accs[cm], vOut);
    }
    __syncthreads();
    for (int c = threadIdx.x; c < kOut; c += blockDim.x)
        A2[(size_t)r * kOut + c] = (c == r) ? 0.0f : accs[c];
}

// ---------------- sparse GCN propagation (fused epilogue) ----------------

// level 0: out[i,c] = ep( sum_{row i CSR} T2[col,c] )
__global__ void k_spmm0_ep(const int* __restrict__ rp, const int* __restrict__ colA,
                           const float* __restrict__ T2, const float* __restrict__ T1,
                           const float* __restrict__ dis, const float* __restrict__ b,
                           float* __restrict__ out, int relu) {
    int i = blockIdx.x, c = threadIdx.x;
    int s = rp[i], e = rp[i + 1];
    float acc = 0.0f;
    for (int t = s; t < e; t++) acc += T2[colA[t] * HID + c];
    float di = dis[i];
    float v = di * (acc + 2.0f * di * T1[i * HID + c]) + b[c];
    if (relu) v = fmaxf(v, 0.0f);
    out[i * HID + c] = v;
}

// level 1: value-weighted sparse rows
__global__ void k_spmm1_ep(const int* __restrict__ oCols, const float* __restrict__ oVals,
                           const int* __restrict__ oCnt,
                           const float* __restrict__ T2, const float* __restrict__ T1,
                           const float* __restrict__ dis, const float* __restrict__ b,
                           float* __restrict__ out, int relu) {
    int i = blockIdx.x, c = threadIdx.x;
    int cnt = oCnt[i];
    const int*   cols = oCols + (size_t)i * 2048;
    const float* vals = oVals + (size_t)i * 2048;
    float acc = 0.0f;
    for (int t = 0; t < cnt; t++) acc += vals[t] * T2[cols[t] * HID + c];
    float di = dis[i];
    float v = di * (acc + 2.0f * di * T1[i * HID + c]) + b[c];
    if (relu) v = fmaxf(v, 0.0f);
    out[i * HID + c] = v;
}

// ---------------- dense kernels ----------------

__global__ void k_encoder(const float* __restrict__ x, const float* __restrict__ W,
                          const float* __restrict__ b, float* __restrict__ h) {
    int i = blockIdx.x;
    int c = threadIdx.x;
    float acc = b[c];
#pragma unroll
    for (int k = 0; k < 16; k++) acc += x[i * 16 + k] * W[k * HID + c];
    h[i * HID + c] = acc;
}

// Register-blocked SGEMM with fused epilogues.
// mode 0: C = acc; if C2 != null also C2 = dis[gm] * acc   (h@W producing T1 and T2)
// mode 1: C = acc with zeroed diagonal                      (augment)
// mode 2: C = [relu]( dis[gm]*(acc + 2*dis[gm]*T1ep[gm*N+gn]) + bias[gn] )  (A@T2 + GCN epilogue)
template <int BM, int BN, int BK, int TM, int TN>
__global__ void k_gemm(const float* __restrict__ A, const float* __restrict__ B,
                       float* __restrict__ C, int M, int N, int K, int mode,
                       const float* __restrict__ dis, const float* __restrict__ T1ep,
                       const float* __restrict__ bias, float* __restrict__ C2, int relu) {
    __shared__ float As[BK][BM];
    __shared__ float Bs[BK][BN];
    const int NT = (BM / TM) * (BN / TN);
    int tid = threadIdx.x;
    int m0 = blockIdx.y * BM, n0 = blockIdx.x * BN;
    int tm = (tid / (BN / TN)) * TM;
    int tn = (tid % (BN / TN)) * TN;
    float acc[TM][TN];
#pragma unroll
    for (int a = 0; a < TM; a++)
#pragma unroll
        for (int b = 0; b < TN; b++) acc[a][b] = 0.0f;

    for (int k0 = 0; k0 < K; k0 += BK) {
        for (int i = tid; i < BM * BK; i += NT) {
            int mm = i / BK, kk = i % BK;
            int gm = m0 + mm, gk = k0 + kk;
            As[kk][mm] = (gm < M && gk < K) ? A[(size_t)gm * K + gk] : 0.0f;
        }
        for (int i = tid; i < BK * BN; i += NT) {
            int kk = i / BN, nn = i % BN;
            int gk = k0 + kk, gn = n0 + nn;
            Bs[kk][nn] = (gk < K && gn < N) ? B[(size_t)gk * N + gn] : 0.0f;
        }
        __syncthreads();
#pragma unroll
        for (int kk = 0; kk < BK; kk++) {
            float ar[TM], br[TN];
#pragma unroll
            for (int a = 0; a < TM; a++) ar[a] = As[kk][tm + a];
#pragma unroll
            for (int b = 0; b < TN; b++) br[b] = Bs[kk][tn + b];
#pragma unroll
            for (int a = 0; a < TM; a++)
#pragma unroll
                for (int b = 0; b < TN; b++) acc[a][b] += ar[a] * br[b];
        }
        __syncthreads();
    }
#pragma unroll
    for (int a = 0; a < TM; a++)
#pragma unroll
        for (int b = 0; b < TN; b++) {
            int gm = m0 + tm + a, gn = n0 + tn + b;
            if (gm < M && gn < N) {
                float v = acc[a][b];
                if (mode == 1) {
                    if (gm == gn) v = 0.0f;
                    C[(size_t)gm * N + gn] = v;
                } else if (mode == 2) {
                    float di = dis[gm];
                    float o = di * (v + 2.0f * di * T1ep[(size_t)gm * N + gn]) + bias[gn];
                    if (relu) o = fmaxf(o, 0.0f);
                    C[(size_t)gm * N + gn] = o;
                } else {
                    C[(size_t)gm * N + gn] = v;
                    if (C2) C2[(size_t)gm * N + gn] = dis[gm] * v;
                }
            }
        }
}

// P[r, m] = B[perm[r], m], B = offdiag(A) + I (dense A)
__global__ void k_gather_rows(const float* __restrict__ A, const int* __restrict__ perm,
                              float* __restrict__ P, int k, int n) {
    size_t idx = (size_t)blockIdx.x * blockDim.x + threadIdx.x;
    if (idx < (size_t)k * n) {
        int r = (int)(idx / n), m = (int)(idx % n);
        int pr = perm[r];
        float v = A[(size_t)pr * n + m];
        P[idx] = (m == pr) ? 1.0f : v;
    }
}

// Q[m, c] = B[m, perm[c]], B = offdiag(A) + I (dense A)
__global__ void k_gather_cols(const float* __restrict__ A, const int* __restrict__ perm,
                              float* __restrict__ Q, int k, int n) {
    size_t idx = (size_t)blockIdx.x * blockDim.x + threadIdx.x;
    if (idx < (size_t)n * k) {
        int m = (int)(idx / k), c = (int)(idx % k);
        int pc = perm[c];
        float v = A[(size_t)m * n + pc];
        Q[idx] = (m == pc) ? 1.0f : v;
    }
}

// dis[i] = rsqrt(rowsum(A[i,:]) + 2)  (dense A)
__global__ void k_dis(const float* __restrict__ A, float* __restrict__ dis, int n) {
    int i = blockIdx.x;
    float s = 0.0f;
    for (int j = threadIdx.x; j < n; j += blockDim.x) s += A[(size_t)i * n + j];
    __shared__ float sm[256];
    sm[threadIdx.x] = s;
    __syncthreads();
    for (int o = 128; o > 0; o >>= 1) {
        if (threadIdx.x < o) sm[threadIdx.x] += sm[threadIdx.x + o];
        __syncthreads();
    }
    if (threadIdx.x == 0) dis[i] = rsqrtf(sm[0] + 2.0f);
}

// ---------------- pooling ----------------

__global__ void k_pnorm(const float* __restrict__ p_pool, float* __restrict__ pn) {
    int r = blockIdx.x;
    float v = p_pool[r * HID + threadIdx.x];
    __shared__ float sm[HID];
    sm[threadIdx.x] = v * v;
    __syncthreads();
    for (int o = 64; o > 0; o >>= 1) {
        if (threadIdx.x < o) sm[threadIdx.x] += sm[threadIdx.x + o];
        __syncthreads();
    }
    if (threadIdx.x == 0) pn[r] = sqrtf(sm[0]);
}

__global__ void k_score(const float* __restrict__ h, const float* __restrict__ p,
                        const float* __restrict__ pn, int lvl, float* __restrict__ score) {
    int i = blockIdx.x;
    __shared__ float sm[HID];
    sm[threadIdx.x] = h[i * HID + threadIdx.x] * p[threadIdx.x];
    __syncthreads();
    for (int o = 64; o > 0; o >>= 1) {
        if (threadIdx.x < o) sm[threadIdx.x] += sm[threadIdx.x + o];
        __syncthreads();
    }
    if (threadIdx.x == 0) score[i] = sm[0] / pn[lvl];
}

__global__ void k_topk_sort(const float* __restrict__ score, int n, int k,
                            int* __restrict__ perm, float* __restrict__ vals) {
    __shared__ float ss[4096];
    __shared__ int   si[4096];
    for (int i = threadIdx.x; i < n; i += blockDim.x) { ss[i] = score[i]; si[i] = i; }
    __syncthreads();
    for (int ksz = 2; ksz <= n; ksz <<= 1) {
        for (int j = ksz >> 1; j > 0; j >>= 1) {
            for (int idx = threadIdx.x; idx < n; idx += blockDim.x) {
                int ixj = idx ^ j;
                if (ixj > idx) {
                    float a = ss[idx], b = ss[ixj];
                    int ai = si[idx], bi = si[ixj];
                    bool beforeBA = (b > a) || (b == a && bi < ai);
                    bool beforeAB = (a > b) || (a == b && ai < bi);
                    bool sw = ((idx & ksz) == 0) ? beforeBA : beforeAB;
                    if (sw) { ss[idx] = b; ss[ixj] = a; si[idx] = bi; si[ixj] = ai; }
                }
            }
            __syncthreads();
        }
    }
    for (int r = threadIdx.x; r < k; r += blockDim.x) { perm[r] = si[r]; vals[r] = ss[r]; }
}

__global__ void k_pool(const float* __restrict__ h, const int* __restrict__ perm,
                       const float* __restrict__ vals, float* __restrict__ hp) {
    int r = blockIdx.x, c = threadIdx.x;
    hp[r * HID + c] = h[perm[r] * HID + c] * tanhf(vals[r]);
}

__global__ void k_copy128(const float* __restrict__ src, float* __restrict__ dst) {
    int i = blockIdx.x, c = threadIdx.x;
    dst[i * HID + c] = src[i * HID + c];
}

__global__ void k_scatter_add(const float* __restrict__ hs, const int* __restrict__ perm,
                              float* __restrict__ out) {
    int r = blockIdx.x, c = threadIdx.x;
    out[perm[r] * HID + c] += hs[r * HID + c];  // unique indices
}

// ---------------- final conv ----------------

__global__ void k_hw_out(const float* __restrict__ h, const float* __restrict__ Wout,
                         const float* __restrict__ dis, float* __restrict__ hw,
                         float* __restrict__ g) {
    int i = blockIdx.x;
    __shared__ float sm[HID];
    sm[threadIdx.x] = h[i * HID + threadIdx.x] * Wout[threadIdx.x];
    __syncthreads();
    for (int o = 64; o > 0; o >>= 1) {
        if (threadIdx.x < o) sm[threadIdx.x] += sm[threadIdx.x + o];
        __syncthreads();
    }
    if (threadIdx.x == 0) { hw[i] = sm[0]; g[i] = dis[i] * sm[0]; }
}

__global__ void k_final_sp(const int* __restrict__ rp, const int* __restrict__ colA,
                           const float* __restrict__ g, const float* __restrict__ hw,
                           const float* __restrict__ dis, const float* __restrict__ b,
                           float* __restrict__ out) {
    int i = blockIdx.x * blockDim.x + threadIdx.x;
    if (i < N0) {
        float s = 0.0f;
        int a = rp[i], e = rp[i + 1];
        for (int t = a; t < e; t++) s += g[colA[t]];
        float di = dis[i];
        out[i] = di * (s + 2.0f * di * hw[i]) + b[0];
    }
}

// ---------------- host orchestration ----------------

static void gemm_hW(const float* hin, const float* W, float* T1, float* T2,
                    const float* dis, int n) {
    dim3 g(HID / 32, n / 32);
    k_gemm<32, 32, 32, 2, 2><<<g, 256>>>(hin, W, T1, n, HID, HID, 0, dis, nullptr,
                                         nullptr, T2, 0);
}

static void gcn_dense(const float* A, int n, const float* hin, const float* W, const float* b,
                      float* hout, int relu, float* T1, float* T2, float* dis) {
    k_dis<<<n, 256>>>(A, dis, n);
    gemm_hW(hin, W, T1, T2, dis, n);
    dim3 g(HID / 32, n / 32);
    k_gemm<32, 32, 32, 2, 2><<<g, 256>>>(A, T2, hout, n, HID, n, 2, dis, T1, b,
                                         nullptr, relu);
}

extern "C" void kernel_launch(void* const* d_in, const int* in_sizes, int n_in,
                              void* d_out, int out_size) {
    const float* x      = (const float*)d_in[0];
    const int*   ei     = (const int*)d_in[1];
    const float* W_enc  = (const float*)d_in[3];
    const float* b_enc  = (const float*)d_in[4];
    const float* W_down = (const float*)d_in[5];
    const float* b_down = (const float*)d_in[6];
    const float* W_up   = (const float*)d_in[7];
    const float* b_up   = (const float*)d_in[8];
    const float* W_out  = (const float*)d_in[9];
    const float* b_out  = (const float*)d_in[10];
    const float* p_pool = (const float*)d_in[11];
    float* out = (float*)d_out;

    float *A2, *A3, *A4, *Pb, *Qb;
    float *X0, *X1, *X2, *X3, *Ha, *Hb, *T1, *T2;
    float *Dis, *Score, *Vals, *HWo, *Gv, *Pn;
    float *A1vals, *A1rsum;
    int *A1cols, *A1cnt;
    int *P0, *P1, *P2, *P3, *Inv, *Rp, *ColA, *Cnt, *Cur;
    cudaGetSymbolAddress((void**)&A1cols, dA1cols);
    cudaGetSymbolAddress((void**)&A1vals, dA1vals);
    cudaGetSymbolAddress((void**)&A1cnt, dA1cnt);
    cudaGetSymbolAddress((void**)&A1rsum, dA1rsum);
    cudaGetSymbolAddress((void**)&A2, dA2);
    cudaGetSymbolAddress((void**)&A3, dA3);
    cudaGetSymbolAddress((void**)&A4, dA4);
    cudaGetSymbolAddress((void**)&Pb, dPbuf);
    cudaGetSymbolAddress((void**)&Qb, dQbuf);
    cudaGetSymbolAddress((void**)&X0, dX0);
    cudaGetSymbolAddress((void**)&X1, dX1);
    cudaGetSymbolAddress((void**)&X2, dX2);
    cudaGetSymbolAddress((void**)&X3, dX3);
    cudaGetSymbolAddress((void**)&Ha, dHa);
    cudaGetSymbolAddress((void**)&Hb, dHb);
    cudaGetSymbolAddress((void**)&T1, dT1);
    cudaGetSymbolAddress((void**)&T2, dT2);
    cudaGetSymbolAddress((void**)&Dis, dDis);
    cudaGetSymbolAddress((void**)&Score, dScore);
    cudaGetSymbolAddress((void**)&Vals, dVals);
    cudaGetSymbolAddress((void**)&HWo, dHWo);
    cudaGetSymbolAddress((void**)&Gv, dGv);
    cudaGetSymbolAddress((void**)&Pn, dPn);
    cudaGetSymbolAddress((void**)&P0, dPerm0);
    cudaGetSymbolAddress((void**)&P1, dPerm1);
    cudaGetSymbolAddress((void**)&P2, dPerm2);
    cudaGetSymbolAddress((void**)&P3, dPerm3);
    cudaGetSymbolAddress((void**)&Inv, dInv);
    cudaGetSymbolAddress((void**)&Rp, dRp);
    cudaGetSymbolAddress((void**)&ColA, dColA);
    cudaGetSymbolAddress((void**)&Cnt, dCnt);
    cudaGetSymbolAddress((void**)&Cur, dCur);

    const int ns[5] = {4096, 2048, 1024, 512, 256};
    float* Xs[4] = {X0, X1, X2, X3};
    int*   Ps[4] = {P0, P1, P2, P3};

    // 1) node encoder
    k_encoder<<<N0, HID>>>(x, W_enc, b_enc, Ha);

    // 2) CSR of A0
    k_zero_int<<<N0 / 256, 256>>>(Cnt, N0);
    k_zero_int<<<N0 / 256, 256>>>(Cur, N0);
    k_count<<<EDGES / 256, 256>>>(ei, Cnt);
    k_scan<<<1, 1024>>>(Cnt, Rp);
    k_fill<<<EDGES / 256, 256>>>(ei, Rp, Cur, ColA);
    k_dis0<<<N0 / 256, 256>>>(Cnt, Dis);

    // 3) pool vector norms
    k_pnorm<<<4, HID>>>(p_pool, Pn);

    // 4) down conv 0 (sparse, fused epilogue) -> X0
    gemm_hW(Ha, W_down, T1, T2, Dis, N0);
    k_spmm0_ep<<<N0, HID>>>(Rp, ColA, T2, T1, Dis, b_down, X0, 1);

    // 5) down path
    const float* hprev = X0;
    for (int i = 1; i <= 4; i++) {
        int n = ns[i - 1], k = ns[i];
        k_score<<<n, HID>>>(hprev, p_pool + (size_t)(i - 1) * HID, Pn, i - 1, Score);
        k_topk_sort<<<1, 1024>>>(Score, n, k, Ps[i - 1], Vals);
        k_pool<<<k, HID>>>(hprev, Ps[i - 1], Vals, Ha);

        float* hout = (i < 4) ? Xs[i] : Hb;
        const float* W = W_down + (size_t)i * HID * HID;
        const float* b = b_down + (size_t)i * HID;

        if (i == 1) {
            k_set_neg1<<<(n + 255) / 256, 256>>>(Inv, n);
            k_set_inv<<<(k + 255) / 256, 256>>>(Ps[0], Inv, k);
            k_spgemm1<<<k, 256>>>(Rp, ColA, Ps[0], Inv, A1cols, A1vals, A1cnt, A1rsum);
            // sparse GCN on A1
            k_dis_rsum<<<(k + 255) / 256, 256>>>(A1rsum, Dis, k);
            gemm_hW(Ha, W, T1, T2, Dis, k);
            k_spmm1_ep<<<k, HID>>>(A1cols, A1vals, A1cnt, T2, T1, Dis, b, hout, 1);
        } else if (i == 2) {
            k_set_neg1<<<(n + 255) / 256, 256>>>(Inv, n);
            k_set_inv<<<(k + 255) / 256, 256>>>(Ps[1], Inv, k);
            k_spgemm2<<<k, 256>>>(A1cols, A1vals, A1cnt, Ps[1], Inv, A2, k);
            gcn_dense(A2, k, Ha, W, b, hout, 1, T1, T2, Dis);
        } else {
            const float* Aprev = (i == 3) ? A2 : A3;
            float* Acur = (i == 3) ? A3 : A4;
            size_t t = (size_t)k * n;
            k_gather_rows<<<(unsigned)((t + 255) / 256), 256>>>(Aprev, Ps[i - 1], Pb, k, n);
            k_gather_cols<<<(unsigned)((t + 255) / 256), 256>>>(Aprev, Ps[i - 1], Qb, k, n);
            if (i == 3) {
                dim3 gg(k / 64, k / 64);
                k_gemm<64, 64, 16, 4, 4><<<gg, 256>>>(Pb, Qb, Acur, k, k, n, 1,
                                                      nullptr, nullptr, nullptr, nullptr, 0);
            } else {
                dim3 gg(k / 32, k / 32);
                k_gemm<32, 32, 32, 2, 2><<<gg, 256>>>(Pb, Qb, Acur, k, k, n, 1,
                                                      nullptr, nullptr, nullptr, nullptr, 0);
            }
            gcn_dense(Acur, k, Ha, W, b, hout, 1, T1, T2, Dis);
        }
        hprev = hout;
    }

    // 6) up path
    float* hcur = Hb;
    for (int i = 0; i < 4; i++) {
        int j = 3 - i;
        int n = ns[j], k = ns[j + 1];
        k_copy128<<<n, HID>>>(Xs[j], Ha);
        k_scatter_add<<<k, HID>>>(hcur, Ps[j], Ha);
        if (j >= 2) {
            // dense GCN on A2 / A3
            gcn_dense(j == 2 ? A2 : A3, n, Ha, W_up + (size_t)i * HID * HID,
                      b_up + (size_t)i * HID, Hb, 1, T1, T2, Dis);
            hcur = Hb;
        } else if (j == 1) {
            // sparse GCN on A1
            k_dis_rsum<<<(n + 255) / 256, 256>>>(A1rsum, Dis, n);
            gemm_hW(Ha, W_up + (size_t)i * HID * HID, T1, T2, Dis, n);
            k_spmm1_ep<<<n, HID>>>(A1cols, A1vals, A1cnt, T2, T1, Dis,
                                   b_up + (size_t)i * HID, Hb, 1);
            hcur = Hb;
        } else {
            // final GCN conv (HID -> 1) on CSR A0
            k_dis0<<<N0 / 256, 256>>>(Cnt, Dis);
            k_hw_out<<<n, HID>>>(Ha, W_out, Dis, HWo, Gv);
            k_final_sp<<<(n + 127) / 128, 128>>>(Rp, ColA, Gv, HWo, Dis, b_out, out);
        }
    }
}

// round 4
// speedup vs baseline: 6.4009x; 1.2596x over previous
#include <cuda_runtime.h>
#include <math.h>
#include <stdint.h>

#define N0    4096
#define EDGES 65536
#define HID   128

// ---------------- device global scratch ----------------
__device__ int   dA1cols[(size_t)2048 * 2048];
__device__ float dA1vals[(size_t)2048 * 2048];
__device__ int   dA1cnt[2048];
__device__ float dA1rsum[2048];
__device__ float dA2[(size_t)1024 * 1024];
__device__ float dA3[(size_t)512 * 512];
__device__ float dA4[(size_t)256 * 256];
__device__ float dPbuf[(size_t)512 * 1024];
__device__ float dQbuf[(size_t)1024 * 512];
__device__ float dX0[N0 * HID];
__device__ float dX1[2048 * HID];
__device__ float dX2[1024 * HID];
__device__ float dX3[512 * HID];
__device__ float dHa[N0 * HID];
__device__ float dHb[N0 * HID];
__device__ float dT1[N0 * HID];
__device__ float dT2[N0 * HID];
__device__ float dScore[N0];
__device__ float dValsArr[N0];
__device__ float dHWo[N0];
__device__ float dGv[N0];
__device__ int   dPerm0[2048];
__device__ int   dPerm1[1024];
__device__ int   dPerm2[512];
__device__ int   dPerm3[256];
__device__ int   dInv0[4096];
__device__ int   dInv1[2048];
__device__ int   dInv2[1024];
__device__ int   dInv3[512];
__device__ float dDis0[4096];
__device__ float dDis1[2048];
__device__ float dDis2[1024];
__device__ float dDis3[512];
__device__ float dDis4[256];
__device__ float dPn[4];
__device__ int   dRp[N0 + 1];
__device__ int   dColA[EDGES];
__device__ int   dCnt[N0];
__device__ int   dCur[N0];

// ---------------- setup kernels ----------------

__global__ void k_zero_int(int* p, int n) {
    int i = blockIdx.x * blockDim.x + threadIdx.x;
    if (i < n) p[i] = 0;
}

__global__ void k_count(const int* __restrict__ ei, int* __restrict__ cnt) {
    int e = blockIdx.x * blockDim.x + threadIdx.x;
    if (e < EDGES) atomicAdd(&cnt[ei[EDGES + e]], 1);
}

__global__ void k_scan(const int* __restrict__ cnt, int* __restrict__ rp) {
    __shared__ int buf[N0];
    int tid = threadIdx.x;
    for (int i = tid; i < N0; i += 1024) buf[i] = cnt[i];
    __syncthreads();
    for (int off = 1; off < N0; off <<= 1) {
        int v[4];
#pragma unroll
        for (int j = 0; j < 4; j++) {
            int i = tid + j * 1024;
            v[j] = (i >= off) ? buf[i - off] : 0;
        }
        __syncthreads();
#pragma unroll
        for (int j = 0; j < 4; j++) buf[tid + j * 1024] += v[j];
        __syncthreads();
    }
    if (tid == 0) rp[0] = 0;
    for (int i = tid; i < N0; i += 1024) rp[i + 1] = buf[i];
}

__global__ void k_fill(const int* __restrict__ ei, const int* __restrict__ rp,
                       int* __restrict__ cur, int* __restrict__ colA) {
    int e = blockIdx.x * blockDim.x + threadIdx.x;
    if (e < EDGES) {
        int s = ei[e], d = ei[EDGES + e];
        int pos = rp[d] + atomicAdd(&cur[d], 1);
        colA[pos] = s;
    }
}

__global__ void k_dis0(const int* __restrict__ cnt, float* __restrict__ dis) {
    int i = blockIdx.x * blockDim.x + threadIdx.x;
    if (i < N0) dis[i] = rsqrtf((float)cnt[i] + 2.0f);
}

__global__ void k_dis_rsum(const float* __restrict__ rsum, float* __restrict__ dis, int n) {
    int i = blockIdx.x * blockDim.x + threadIdx.x;
    if (i < n) dis[i] = rsqrtf(rsum[i] + 2.0f);
}

__global__ void k_set_neg1(int* __restrict__ inv, int n) {
    int i = blockIdx.x * blockDim.x + threadIdx.x;
    if (i < n) inv[i] = -1;
}

__global__ void k_set_inv(const int* __restrict__ perm, int* __restrict__ inv, int k) {
    int i = blockIdx.x * blockDim.x + threadIdx.x;
    if (i < k) inv[perm[i]] = i;
}

// ---------------- sparse augment ----------------

__global__ void k_spgemm1(const int* __restrict__ rp, const int* __restrict__ colA,
                          const int* __restrict__ perm, const int* __restrict__ inv,
                          int* __restrict__ oCols, float* __restrict__ oVals,
                          int* __restrict__ oCnt, float* __restrict__ oRsum) {
    __shared__ float accs[2048];
    __shared__ int   tpre[256];
    __shared__ float fsum[256];
    int r = blockIdx.x;
    int pr = perm[r];
    for (int i = threadIdx.x; i < 2048; i += blockDim.x) accs[i] = 0.0f;
    __syncthreads();
    int s = rp[pr], e = rp[pr + 1];
    int outerCnt = (e - s) + 1;
    for (int oi = threadIdx.x; oi < outerCnt; oi += blockDim.x) {
        int m = (oi < e - s) ? colA[s + oi] : pr;
        if (oi < e - s && m == pr) continue;
        int s2 = rp[m], e2 = rp[m + 1];
        for (int t = s2; t < e2; t++) {
            int j = colA[t];
            if (j == m) continue;
            int c = inv[j];
            if (c >= 0) atomicAdd(&accs[c], 1.0f);
        }
        int cm = inv[m];
        if (cm >= 0) atomicAdd(&accs[cm], 1.0f);
    }
    __syncthreads();
    int base = threadIdx.x * 8;
    int lc = 0;
    float ls = 0.0f;
#pragma unroll
    for (int j = 0; j < 8; j++) {
        int c = base + j;
        float v = accs[c];
        if (c != r && v != 0.0f) { lc++; ls += v; }
    }
    tpre[threadIdx.x] = lc;
    fsum[threadIdx.x] = ls;
    __syncthreads();
    for (int off = 1; off < 256; off <<= 1) {
        int v = (threadIdx.x >= off) ? tpre[threadIdx.x - off] : 0;
        float f = (threadIdx.x >= off) ? fsum[threadIdx.x - off] : 0.0f;
        __syncthreads();
        tpre[threadIdx.x] += v;
        fsum[threadIdx.x] += f;
        __syncthreads();
    }
    int pos = tpre[threadIdx.x] - lc;
#pragma unroll
    for (int j = 0; j < 8; j++) {
        int c = base + j;
        float v = accs[c];
        if (c != r && v != 0.0f) {
            oCols[(size_t)r * 2048 + pos] = c;
            oVals[(size_t)r * 2048 + pos] = v;
            pos++;
        }
    }
    if (threadIdx.x == 255) { oCnt[r] = tpre[255]; oRsum[r] = fsum[255]; }
}

__global__ void k_spgemm2(const int* __restrict__ oCols, const float* __restrict__ oVals,
                          const int* __restrict__ oCnt,
                          const int* __restrict__ perm, const int* __restrict__ inv,
                          float* __restrict__ A2, int kOut) {
    __shared__ float accs[1024];
    int r = blockIdx.x;
    int pr = perm[r];
    for (int i = threadIdx.x; i < kOut; i += blockDim.x) accs[i] = 0.0f;
    __syncthreads();
    int cnt = oCnt[pr];
    const int*   cols = oCols + (size_t)pr * 2048;
    const float* vals = oVals + (size_t)pr * 2048;
    int outerCnt = cnt + 1;
    for (int oi = threadIdx.x; oi < outerCnt; oi += blockDim.x) {
        int m; float vOut;
        if (oi < cnt) { m = cols[oi]; vOut = vals[oi]; }
        else          { m = pr;       vOut = 1.0f; }
        int cnt2 = oCnt[m];
        const int*   cols2 = oCols + (size_t)m * 2048;
        const float* vals2 = oVals + (size_t)m * 2048;
        for (int t = 0; t < cnt2; t++) {
            int c = inv[cols2[t]];
            if (c >= 0) atomicAdd(&accs[c], vOut * vals2[t]);
        }
        int cm = inv[m];
        if (cm >= 0) atomicAdd(&accs[cm], vOut);
    }
    __syncthreads();
    for (int c = threadIdx.x; c < kOut; c += blockDim.x)
        A2[(size_t)r * kOut + c] = (c == r) ? 0.0f : accs[c];
}

// ---------------- sparse GCN propagation (fused epilogue) ----------------

__global__ void k_spmm0_ep(const int* __restrict__ rp, const int* __restrict__ colA,
                           const float* __restrict__ T2, const float* __restrict__ T1,
                           const float* __restrict__ dis, const float* __restrict__ b,
                           float* __restrict__ out, int relu) {
    int i = blockIdx.x, c = threadIdx.x;
    int s = rp[i], e = rp[i + 1];
    float acc = 0.0f;
    for (int t = s; t < e; t++) acc += T2[colA[t] * HID + c];
    float di = dis[i];
    float v = di * (acc + 2.0f * di * T1[i * HID + c]) + b[c];
    if (relu) v = fmaxf(v, 0.0f);
    out[i * HID + c] = v;
}

__global__ void k_spmm1_ep(const int* __restrict__ oCols, const float* __restrict__ oVals,
                           const int* __restrict__ oCnt,
                           const float* __restrict__ T2, const float* __restrict__ T1,
                           const float* __restrict__ dis, const float* __restrict__ b,
                           float* __restrict__ out, int relu) {
    int i = blockIdx.x, c = threadIdx.x;
    int cnt = oCnt[i];
    const int*   cols = oCols + (size_t)i * 2048;
    const float* vals = oVals + (size_t)i * 2048;
    float acc = 0.0f;
    for (int t = 0; t < cnt; t++) acc += vals[t] * T2[cols[t] * HID + c];
    float di = dis[i];
    float v = di * (acc + 2.0f * di * T1[i * HID + c]) + b[c];
    if (relu) v = fmaxf(v, 0.0f);
    out[i * HID + c] = v;
}

// ---------------- dense kernels ----------------

__global__ void k_encoder(const float* __restrict__ x, const float* __restrict__ W,
                          const float* __restrict__ b, float* __restrict__ h) {
    int i = blockIdx.x;
    int c = threadIdx.x;
    float acc = b[c];
#pragma unroll
    for (int k = 0; k < 16; k++) acc += x[i * 16 + k] * W[k * HID + c];
    h[i * HID + c] = acc;
}

// Fast SGEMM: 64x64x16 tiles, 256 threads, TM=TN=4, float4 everywhere.
// REQUIRES: M,N multiples of 64; K multiple of 16; 16B-aligned pointers.
// mode 0: C = acc; if C2 != null also C2 = dis[gm] * acc
// mode 1: C = acc, diag zeroed
// mode 2: C = [relu]( dis[gm]*(acc + 2*dis[gm]*T1ep[gm*N+gn]) + bias[gn] )
__global__ void k_gemm64(const float* __restrict__ A, const float* __restrict__ B,
                         float* __restrict__ C, int M, int N, int K, int mode,
                         const float* __restrict__ dis, const float* __restrict__ T1ep,
                         const float* __restrict__ bias, float* __restrict__ C2, int relu) {
    __shared__ float As[16][64];
    __shared__ float Bs[16][64];
    int t = threadIdx.x;
    int m0 = blockIdx.y * 64, n0 = blockIdx.x * 64;
    // A tile load map: row = t/4 (0..63), col group = (t%4)*4
    int ar_ = t >> 2, ac_ = (t & 3) << 2;
    // B tile load map: kk = t/16 (0..15), col group = (t%16)*4
    int bk_ = t >> 4, bn_ = (t & 15) << 2;
    // compute map
    int tm = (t >> 4) << 2, tn = (t & 15) << 2;
    float acc[4][4];
#pragma unroll
    for (int a = 0; a < 4; a++)
#pragma unroll
        for (int b = 0; b < 4; b++) acc[a][b] = 0.0f;

    const float* Aptr = A + (size_t)(m0 + ar_) * K + ac_;
    const float* Bptr = B + (size_t)bk_ * N + n0 + bn_;
    for (int k0 = 0; k0 < K; k0 += 16) {
        float4 av = *(const float4*)(Aptr + k0);
        As[ac_ + 0][ar_] = av.x;
        As[ac_ + 1][ar_] = av.y;
        As[ac_ + 2][ar_] = av.z;
        As[ac_ + 3][ar_] = av.w;
        *(float4*)&Bs[bk_][bn_] = *(const float4*)(Bptr + (size_t)k0 * N);
        __syncthreads();
#pragma unroll
        for (int kk = 0; kk < 16; kk++) {
            float4 a4 = *(const float4*)&As[kk][tm];
            float4 b4 = *(const float4*)&Bs[kk][tn];
            float ar[4] = {a4.x, a4.y, a4.z, a4.w};
            float br[4] = {b4.x, b4.y, b4.z, b4.w};
#pragma unroll
            for (int a = 0; a < 4; a++)
#pragma unroll
                for (int b = 0; b < 4; b++) acc[a][b] += ar[a] * br[b];
        }
        __syncthreads();
    }
#pragma unroll
    for (int a = 0; a < 4; a++) {
        int gm = m0 + tm + a;
#pragma unroll
        for (int b = 0; b < 4; b++) {
            int gn = n0 + tn + b;
            float v = acc[a][b];
            if (mode == 1) {
                if (gm == gn) v = 0.0f;
                C[(size_t)gm * N + gn] = v;
            } else if (mode == 2) {
                float di = dis[gm];
                float o = di * (v + 2.0f * di * T1ep[(size_t)gm * N + gn]) + bias[gn];
                if (relu) o = fmaxf(o, 0.0f);
                C[(size_t)gm * N + gn] = o;
            } else {
                C[(size_t)gm * N + gn] = v;
                if (C2) C2[(size_t)gm * N + gn] = dis[gm] * v;
            }
        }
    }
}

__global__ void k_gather_rows(const float* __restrict__ A, const int* __restrict__ perm,
                              float* __restrict__ P, int k, int n) {
    size_t idx = (size_t)blockIdx.x * blockDim.x + threadIdx.x;
    if (idx < (size_t)k * n) {
        int r = (int)(idx / n), m = (int)(idx % n);
        int pr = perm[r];
        float v = A[(size_t)pr * n + m];
        P[idx] = (m == pr) ? 1.0f : v;
    }
}

__global__ void k_gather_cols(const float* __restrict__ A, const int* __restrict__ perm,
                              float* __restrict__ Q, int k, int n) {
    size_t idx = (size_t)blockIdx.x * blockDim.x + threadIdx.x;
    if (idx < (size_t)n * k) {
        int m = (int)(idx / k), c = (int)(idx % k);
        int pc = perm[c];
        float v = A[(size_t)m * n + pc];
        Q[idx] = (m == pc) ? 1.0f : v;
    }
}

__global__ void k_dis(const float* __restrict__ A, float* __restrict__ dis, int n) {
    int i = blockIdx.x;
    float s = 0.0f;
    for (int j = threadIdx.x; j < n; j += blockDim.x) s += A[(size_t)i * n + j];
    __shared__ float sm[256];
    sm[threadIdx.x] = s;
    __syncthreads();
    for (int o = 128; o > 0; o >>= 1) {
        if (threadIdx.x < o) sm[threadIdx.x] += sm[threadIdx.x + o];
        __syncthreads();
    }
    if (threadIdx.x == 0) dis[i] = rsqrtf(sm[0] + 2.0f);
}

// ---------------- pooling ----------------

__global__ void k_pnorm(const float* __restrict__ p_pool, float* __restrict__ pn) {
    int r = blockIdx.x;
    float v = p_pool[r * HID + threadIdx.x];
    __shared__ float sm[HID];
    sm[threadIdx.x] = v * v;
    __syncthreads();
    for (int o = 64; o > 0; o >>= 1) {
        if (threadIdx.x < o) sm[threadIdx.x] += sm[threadIdx.x + o];
        __syncthreads();
    }
    if (threadIdx.x == 0) pn[r] = sqrtf(sm[0]);
}

__global__ void k_score(const float* __restrict__ h, const float* __restrict__ p,
                        const float* __restrict__ pn, int lvl, float* __restrict__ score) {
    int i = blockIdx.x;
    __shared__ float sm[HID];
    sm[threadIdx.x] = h[i * HID + threadIdx.x] * p[threadIdx.x];
    __syncthreads();
    for (int o = 64; o > 0; o >>= 1) {
        if (threadIdx.x < o) sm[threadIdx.x] += sm[threadIdx.x + o];
        __syncthreads();
    }
    if (threadIdx.x == 0) score[i] = sm[0] / pn[lvl];
}

// Packed-key bitonic sort: descending by score, ties -> lower index first.
__global__ void k_topk_sort(const float* __restrict__ score, int n, int k,
                            int* __restrict__ perm, float* __restrict__ vals) {
    __shared__ unsigned long long key[4096];
    int tid = threadIdx.x;
    for (int i = tid; i < n; i += blockDim.x) {
        unsigned u = __float_as_uint(score[i]);
        u = (u & 0x80000000u) ? ~u : (u | 0x80000000u);
        key[i] = ((unsigned long long)u << 32) | (unsigned)(~i);
    }
    __syncthreads();
    for (int ksz = 2; ksz <= n; ksz <<= 1) {
        for (int j = ksz >> 1; j > 0; j >>= 1) {
            for (int idx = tid; idx < n; idx += blockDim.x) {
                int ixj = idx ^ j;
                if (ixj > idx) {
                    unsigned long long a = key[idx], b = key[ixj];
                    bool sw = ((idx & ksz) == 0) ? (b > a) : (a > b);
                    if (sw) { key[idx] = b; key[ixj] = a; }
                }
            }
            __syncthreads();
        }
    }
    for (int r = tid; r < k; r += blockDim.x) {
        int idx = (int)(~(unsigned)key[r]);
        perm[r] = idx;
        vals[r] = score[idx];
    }
}

__global__ void k_pool(const float* __restrict__ h, const int* __restrict__ perm,
                       const float* __restrict__ vals, float* __restrict__ hp) {
    int r = blockIdx.x, c = threadIdx.x;
    hp[r * HID + c] = h[perm[r] * HID + c] * tanhf(vals[r]);
}

// fused unpool: out[i] = X[i] + (inv[i] >= 0 ? h[inv[i]] : 0)
__global__ void k_unpool(const float* __restrict__ X, const float* __restrict__ h,
                         const int* __restrict__ inv, float* __restrict__ out) {
    int i = blockIdx.x, c = threadIdx.x;
    float v = X[i * HID + c];
    int r = inv[i];
    if (r >= 0) v += h[r * HID + c];
    out[i * HID + c] = v;
}

// ---------------- final conv ----------------

__global__ void k_hw_out(const float* __restrict__ h, const float* __restrict__ Wout,
                         const float* __restrict__ dis, float* __restrict__ hw,
                         float* __restrict__ g) {
    int i = blockIdx.x;
    __shared__ float sm[HID];
    sm[threadIdx.x] = h[i * HID + threadIdx.x] * Wout[threadIdx.x];
    __syncthreads();
    for (int o = 64; o > 0; o >>= 1) {
        if (threadIdx.x < o) sm[threadIdx.x] += sm[threadIdx.x + o];
        __syncthreads();
    }
    if (threadIdx.x == 0) { hw[i] = sm[0]; g[i] = dis[i] * sm[0]; }
}

__global__ void k_final_sp(const int* __restrict__ rp, const int* __restrict__ colA,
                           const float* __restrict__ g, const float* __restrict__ hw,
                           const float* __restrict__ dis, const float* __restrict__ b,
                           float* __restrict__ out) {
    int i = blockIdx.x * blockDim.x + threadIdx.x;
    if (i < N0) {
        float s = 0.0f;
        int a = rp[i], e = rp[i + 1];
        for (int t = a; t < e; t++) s += g[colA[t]];
        float di = dis[i];
        out[i] = di * (s + 2.0f * di * hw[i]) + b[0];
    }
}

// ---------------- host orchestration ----------------

static void gemm_hW(const float* hin, const float* W, float* T1, float* T2,
                    const float* dis, int n) {
    dim3 g(HID / 64, n / 64);
    k_gemm64<<<g, 256>>>(hin, W, T1, n, HID, HID, 0, dis, nullptr, nullptr, T2, 0);
}

static void gcn_dense(const float* A, int n, const float* hin, const float* W, const float* b,
                      float* hout, int relu, float* T1, float* T2, float* dis, bool computeDis) {
    if (computeDis) k_dis<<<n, 256>>>(A, dis, n);
    gemm_hW(hin, W, T1, T2, dis, n);
    dim3 g(HID / 64, n / 64);
    k_gemm64<<<g, 256>>>(A, T2, hout, n, HID, n, 2, dis, T1, b, nullptr, relu);
}

extern "C" void kernel_launch(void* const* d_in, const int* in_sizes, int n_in,
                              void* d_out, int out_size) {
    const float* x      = (const float*)d_in[0];
    const int*   ei     = (const int*)d_in[1];
    const float* W_enc  = (const float*)d_in[3];
    const float* b_enc  = (const float*)d_in[4];
    const float* W_down = (const float*)d_in[5];
    const float* b_down = (const float*)d_in[6];
    const float* W_up   = (const float*)d_in[7];
    const float* b_up   = (const float*)d_in[8];
    const float* W_out  = (const float*)d_in[9];
    const float* b_out  = (const float*)d_in[10];
    const float* p_pool = (const float*)d_in[11];
    float* out = (float*)d_out;

    float *A2, *A3, *A4, *Pb, *Qb;
    float *X0, *X1, *X2, *X3, *Ha, *Hb, *T1, *T2;
    float *Score, *Vals, *HWo, *Gv, *Pn;
    float *A1vals, *A1rsum;
    int *A1cols, *A1cnt;
    int *P0, *P1, *P2, *P3, *Rp, *ColA, *Cnt, *Cur;
    int *I0, *I1, *I2, *I3;
    float *D0, *D1, *D2, *D3, *D4;
    cudaGetSymbolAddress((void**)&A1cols, dA1cols);
    cudaGetSymbolAddress((void**)&A1vals, dA1vals);
    cudaGetSymbolAddress((void**)&A1cnt, dA1cnt);
    cudaGetSymbolAddress((void**)&A1rsum, dA1rsum);
    cudaGetSymbolAddress((void**)&A2, dA2);
    cudaGetSymbolAddress((void**)&A3, dA3);
    cudaGetSymbolAddress((void**)&A4, dA4);
    cudaGetSymbolAddress((void**)&Pb, dPbuf);
    cudaGetSymbolAddress((void**)&Qb, dQbuf);
    cudaGetSymbolAddress((void**)&X0, dX0);
    cudaGetSymbolAddress((void**)&X1, dX1);
    cudaGetSymbolAddress((void**)&X2, dX2);
    cudaGetSymbolAddress((void**)&X3, dX3);
    cudaGetSymbolAddress((void**)&Ha, dHa);
    cudaGetSymbolAddress((void**)&Hb, dHb);
    cudaGetSymbolAddress((void**)&T1, dT1);
    cudaGetSymbolAddress((void**)&T2, dT2);
    cudaGetSymbolAddress((void**)&Score, dScore);
    cudaGetSymbolAddress((void**)&Vals, dValsArr);
    cudaGetSymbolAddress((void**)&HWo, dHWo);
    cudaGetSymbolAddress((void**)&Gv, dGv);
    cudaGetSymbolAddress((void**)&Pn, dPn);
    cudaGetSymbolAddress((void**)&P0, dPerm0);
    cudaGetSymbolAddress((void**)&P1, dPerm1);
    cudaGetSymbolAddress((void**)&P2, dPerm2);
    cudaGetSymbolAddress((void**)&P3, dPerm3);
    cudaGetSymbolAddress((void**)&I0, dInv0);
    cudaGetSymbolAddress((void**)&I1, dInv1);
    cudaGetSymbolAddress((void**)&I2, dInv2);
    cudaGetSymbolAddress((void**)&I3, dInv3);
    cudaGetSymbolAddress((void**)&D0, dDis0);
    cudaGetSymbolAddress((void**)&D1, dDis1);
    cudaGetSymbolAddress((void**)&D2, dDis2);
    cudaGetSymbolAddress((void**)&D3, dDis3);
    cudaGetSymbolAddress((void**)&D4, dDis4);
    cudaGetSymbolAddress((void**)&Rp, dRp);
    cudaGetSymbolAddress((void**)&ColA, dColA);
    cudaGetSymbolAddress((void**)&Cnt, dCnt);
    cudaGetSymbolAddress((void**)&Cur, dCur);

    const int ns[5] = {4096, 2048, 1024, 512, 256};
    float* Xs[4] = {X0, X1, X2, X3};
    int*   Ps[4] = {P0, P1, P2, P3};
    int*   Is[4] = {I0, I1, I2, I3};
    float* Ds[5] = {D0, D1, D2, D3, D4};

    // 1) node encoder
    k_encoder<<<N0, HID>>>(x, W_enc, b_enc, Ha);

    // 2) CSR of A0
    k_zero_int<<<N0 / 256, 256>>>(Cnt, N0);
    k_zero_int<<<N0 / 256, 256>>>(Cur, N0);
    k_count<<<EDGES / 256, 256>>>(ei, Cnt);
    k_scan<<<1, 1024>>>(Cnt, Rp);
    k_fill<<<EDGES / 256, 256>>>(ei, Rp, Cur, ColA);
    k_dis0<<<N0 / 256, 256>>>(Cnt, D0);

    // 3) pool vector norms
    k_pnorm<<<4, HID>>>(p_pool, Pn);

    // 4) down conv 0 (sparse, fused epilogue) -> X0
    gemm_hW(Ha, W_down, T1, T2, D0, N0);
    k_spmm0_ep<<<N0, HID>>>(Rp, ColA, T2, T1, D0, b_down, X0, 1);

    // 5) down path
    const float* hprev = X0;
    for (int i = 1; i <= 4; i++) {
        int n = ns[i - 1], k = ns[i];
        k_score<<<n, HID>>>(hprev, p_pool + (size_t)(i - 1) * HID, Pn, i - 1, Score);
        k_topk_sort<<<1, 1024>>>(Score, n, k, Ps[i - 1], Vals);
        k_pool<<<k, HID>>>(hprev, Ps[i - 1], Vals, Ha);
        // per-level inverse perm (used by augment here and by unpool later)
        k_set_neg1<<<(n + 255) / 256, 256>>>(Is[i - 1], n);
        k_set_inv<<<(k + 255) / 256, 256>>>(Ps[i - 1], Is[i - 1], k);

        float* hout = (i < 4) ? Xs[i] : Hb;
        const float* W = W_down + (size_t)i * HID * HID;
        const float* b = b_down + (size_t)i * HID;

        if (i == 1) {
            k_spgemm1<<<k, 256>>>(Rp, ColA, Ps[0], I0, A1cols, A1vals, A1cnt, A1rsum);
            k_dis_rsum<<<(k + 255) / 256, 256>>>(A1rsum, D1, k);
            gemm_hW(Ha, W, T1, T2, D1, k);
            k_spmm1_ep<<<k, HID>>>(A1cols, A1vals, A1cnt, T2, T1, D1, b, hout, 1);
        } else if (i == 2) {
            k_spgemm2<<<k, 256>>>(A1cols, A1vals, A1cnt, Ps[1], I1, A2, k);
            gcn_dense(A2, k, Ha, W, b, hout, 1, T1, T2, D2, true);
        } else {
            const float* Aprev = (i == 3) ? A2 : A3;
            float* Acur = (i == 3) ? A3 : A4;
            size_t t = (size_t)k * n;
            k_gather_rows<<<(unsigned)((t + 255) / 256), 256>>>(Aprev, Ps[i - 1], Pb, k, n);
            k_gather_cols<<<(unsigned)((t + 255) / 256), 256>>>(Aprev, Ps[i - 1], Qb, k, n);
            dim3 gg(k / 64, k / 64);
            k_gemm64<<<gg, 256>>>(Pb, Qb, Acur, k, k, n, 1, nullptr, nullptr, nullptr,
                                  nullptr, 0);
            gcn_dense(Acur, k, Ha, W, b, hout, 1, T1, T2, Ds[i], true);
        }
        hprev = hout;
    }

    // 6) up path
    float* hcur = Hb;
    for (int i = 0; i < 4; i++) {
        int j = 3 - i;
        int n = ns[j];
        k_unpool<<<n, HID>>>(Xs[j], hcur, Is[j], Ha);
        if (j >= 2) {
            gcn_dense(j == 2 ? A2 : A3, n, Ha, W_up + (size_t)i * HID * HID,
                      b_up + (size_t)i * HID, Hb, 1, T1, T2, Ds[j], false);
            hcur = Hb;
        } else if (j == 1) {
            gemm_hW(Ha, W_up + (size_t)i * HID * HID, T1, T2, D1, n);
            k_spmm1_ep<<<n, HID>>>(A1cols, A1vals, A1cnt, T2, T1, D1,
                                   b_up + (size_t)i * HID, Hb, 1);
            hcur = Hb;
        } else {
            k_hw_out<<<n, HID>>>(Ha, W_out, D0, HWo, Gv);
            k_final_sp<<<(n + 127) / 128, 128>>>(Rp, ColA, Gv, HWo, D0, b_out, out);
        }
    }
}

// round 5
// speedup vs baseline: 12.0452x; 1.8818x over previous
#include <cuda_runtime.h>
#include <math.h>
#include <stdint.h>

#define N0    4096
#define EDGES 65536
#define HID   128

// ---------------- device global scratch ----------------
__device__ int   dA1cols[(size_t)2048 * 2048];
__device__ float dA1vals[(size_t)2048 * 2048];
__device__ int   dA1cnt[2048];
__device__ float dA2[(size_t)1024 * 1024];
__device__ float dA3[(size_t)512 * 512];
__device__ float dA4[(size_t)256 * 256];
__device__ float dSplit[1 << 20];              // split-K partials (4 MB)
__device__ float dPbuf[(size_t)512 * 1024];
__device__ float dQbuf[(size_t)1024 * 512];
__device__ float dX0[N0 * HID];
__device__ float dX1[2048 * HID];
__device__ float dX2[1024 * HID];
__device__ float dX3[512 * HID];
__device__ float dHa[N0 * HID];
__device__ float dHb[N0 * HID];
__device__ float dT1[N0 * HID];
__device__ float dT2[N0 * HID];
__device__ float dScore[N0];
__device__ float dValsArr[N0];
__device__ float dHWo[N0];
__device__ float dGv[N0];
__device__ int   dPerm0[2048];
__device__ int   dPerm1[1024];
__device__ int   dPerm2[512];
__device__ int   dPerm3[256];
__device__ int   dInv0[4096];
__device__ int   dInv1[2048];
__device__ int   dInv2[1024];
__device__ int   dInv3[512];
__device__ float dDis0[4096];
__device__ float dDis1[2048];
__device__ float dDis2[1024];
__device__ float dDis3[512];
__device__ float dDis4[256];
__device__ float dPn[4];
__device__ int   dRp[N0 + 1];
__device__ int   dColA[EDGES];
__device__ int   dCnt[N0];
__device__ int   dCur[N0];

// ---------------- packed f32x2 FMA ----------------
__device__ __forceinline__ void ffma2(unsigned long long& d, unsigned long long a,
                                      unsigned long long b) {
    asm("fma.rn.f32x2 %0, %1, %2, %0;" : "+l"(d) : "l"(a), "l"(b));
}

// ---------------- setup kernels ----------------

__global__ void k_zero2(int* a, int* b, int n) {
    int i = blockIdx.x * blockDim.x + threadIdx.x;
    if (i < n) { a[i] = 0; b[i] = 0; }
}

__global__ void k_count(const int* __restrict__ ei, int* __restrict__ cnt) {
    int e = blockIdx.x * blockDim.x + threadIdx.x;
    if (e < EDGES) atomicAdd(&cnt[ei[EDGES + e]], 1);
}

__global__ void k_scan(const int* __restrict__ cnt, int* __restrict__ rp) {
    __shared__ int buf[N0];
    int tid = threadIdx.x;
    for (int i = tid; i < N0; i += 1024) buf[i] = cnt[i];
    __syncthreads();
    for (int off = 1; off < N0; off <<= 1) {
        int v[4];
#pragma unroll
        for (int j = 0; j < 4; j++) {
            int i = tid + j * 1024;
            v[j] = (i >= off) ? buf[i - off] : 0;
        }
        __syncthreads();
#pragma unroll
        for (int j = 0; j < 4; j++) buf[tid + j * 1024] += v[j];
        __syncthreads();
    }
    if (tid == 0) rp[0] = 0;
    for (int i = tid; i < N0; i += 1024) rp[i + 1] = buf[i];
}

__global__ void k_fill(const int* __restrict__ ei, const int* __restrict__ rp,
                       int* __restrict__ cur, int* __restrict__ colA) {
    int e = blockIdx.x * blockDim.x + threadIdx.x;
    if (e < EDGES) {
        int s = ei[e], d = ei[EDGES + e];
        int pos = rp[d] + atomicAdd(&cur[d], 1);
        colA[pos] = s;
    }
}

__global__ void k_dis0(const int* __restrict__ cnt, float* __restrict__ dis) {
    int i = blockIdx.x * blockDim.x + threadIdx.x;
    if (i < N0) dis[i] = rsqrtf((float)cnt[i] + 2.0f);
}

// ---------------- sparse augment ----------------

// Level-1: A1 = offdiag((B@B)[perm,perm]) sparse; also writes dis1.
__global__ void k_spgemm1(const int* __restrict__ rp, const int* __restrict__ colA,
                          const int* __restrict__ perm, const int* __restrict__ inv,
                          int* __restrict__ oCols, float* __restrict__ oVals,
                          int* __restrict__ oCnt, float* __restrict__ dis1) {
    __shared__ float accs[2048];
    __shared__ int   tpre[256];
    __shared__ float fsum[256];
    int r = blockIdx.x;
    int pr = perm[r];
    for (int i = threadIdx.x; i < 2048; i += blockDim.x) accs[i] = 0.0f;
    __syncthreads();
    int s = rp[pr], e = rp[pr + 1];
    int outerCnt = (e - s) + 1;
    for (int oi = threadIdx.x; oi < outerCnt; oi += blockDim.x) {
        int m = (oi < e - s) ? colA[s + oi] : pr;
        if (oi < e - s && m == pr) continue;
        int s2 = rp[m], e2 = rp[m + 1];
        for (int t = s2; t < e2; t++) {
            int j = colA[t];
            if (j == m) continue;
            int c = inv[j];
            if (c >= 0) atomicAdd(&accs[c], 1.0f);
        }
        int cm = inv[m];
        if (cm >= 0) atomicAdd(&accs[cm], 1.0f);
    }
    __syncthreads();
    int base = threadIdx.x * 8;
    int lc = 0;
    float ls = 0.0f;
#pragma unroll
    for (int j = 0; j < 8; j++) {
        int c = base + j;
        float v = accs[c];
        if (c != r && v != 0.0f) { lc++; ls += v; }
    }
    tpre[threadIdx.x] = lc;
    fsum[threadIdx.x] = ls;
    __syncthreads();
    for (int off = 1; off < 256; off <<= 1) {
        int v = (threadIdx.x >= off) ? tpre[threadIdx.x - off] : 0;
        float f = (threadIdx.x >= off) ? fsum[threadIdx.x - off] : 0.0f;
        __syncthreads();
        tpre[threadIdx.x] += v;
        fsum[threadIdx.x] += f;
        __syncthreads();
    }
    int pos = tpre[threadIdx.x] - lc;
#pragma unroll
    for (int j = 0; j < 8; j++) {
        int c = base + j;
        float v = accs[c];
        if (c != r && v != 0.0f) {
            oCols[(size_t)r * 2048 + pos] = c;
            oVals[(size_t)r * 2048 + pos] = v;
            pos++;
        }
    }
    if (threadIdx.x == 255) {
        oCnt[r] = tpre[255];
        dis1[r] = rsqrtf(fsum[255] + 2.0f);
    }
}

// Level-2: A2 dense = offdiag((B1@B1)[perm,perm]); warp-per-outer, coalesced
// inner-row loads; fused diag-zero row write + rowsum -> dis2.
__global__ void k_spgemm2(const int* __restrict__ oCols, const float* __restrict__ oVals,
                          const int* __restrict__ oCnt,
                          const int* __restrict__ perm, const int* __restrict__ invg,
                          float* __restrict__ A2, float* __restrict__ dis2, int kOut) {
    __shared__ float accs[1024];
    __shared__ int   sinv[2048];
    __shared__ float red[8];
    int r = blockIdx.x;
    int pr = perm[r];
    int tid = threadIdx.x;
    for (int i = tid; i < kOut; i += 256) accs[i] = 0.0f;
    for (int i = tid; i < 2048; i += 256) sinv[i] = invg[i];
    __syncthreads();
    int cnt = oCnt[pr];
    const int*   cols = oCols + (size_t)pr * 2048;
    const float* vals = oVals + (size_t)pr * 2048;
    int lane = tid & 31, w = tid >> 5;
    for (int oi = w; oi <= cnt; oi += 8) {
        int m; float vOut;
        if (oi < cnt) { m = cols[oi]; vOut = vals[oi]; }
        else          { m = pr;       vOut = 1.0f; }
        int cnt2 = oCnt[m];
        const int*   cols2 = oCols + (size_t)m * 2048;
        const float* vals2 = oVals + (size_t)m * 2048;
        for (int t2 = lane; t2 < cnt2; t2 += 32) {
            int c = sinv[cols2[t2]];
            if (c >= 0) atomicAdd(&accs[c], vOut * vals2[t2]);
        }
        if (lane == 0) {
            int cm = sinv[m];
            if (cm >= 0) atomicAdd(&accs[cm], vOut);
        }
    }
    __syncthreads();
    float s = 0.0f;
    for (int c = tid; c < kOut; c += 256) {
        float v = (c == r) ? 0.0f : accs[c];
        s += v;
        A2[(size_t)r * kOut + c] = v;
    }
#pragma unroll
    for (int off = 16; off; off >>= 1) s += __shfl_down_sync(0xffffffffu, s, off);
    if (lane == 0) red[w] = s;
    __syncthreads();
    if (tid == 0) {
        float tot = 0.0f;
#pragma unroll
        for (int i = 0; i < 8; i++) tot += red[i];
        dis2[r] = rsqrtf(tot + 2.0f);
    }
}

// ---------------- sparse GCN propagation (fused epilogue) ----------------

__global__ void k_spmm0_ep(const int* __restrict__ rp, const int* __restrict__ colA,
                           const float* __restrict__ T2, const float* __restrict__ T1,
                           const float* __restrict__ dis, const float* __restrict__ b,
                           float* __restrict__ out, int relu) {
    int i = blockIdx.x, c = threadIdx.x;
    int s = rp[i], e = rp[i + 1];
    float acc = 0.0f;
    for (int t = s; t < e; t++) acc += T2[colA[t] * HID + c];
    float di = dis[i];
    float v = di * (acc + 2.0f * di * T1[i * HID + c]) + b[c];
    if (relu) v = fmaxf(v, 0.0f);
    out[i * HID + c] = v;
}

__global__ void k_spmm1_ep(const int* __restrict__ oCols, const float* __restrict__ oVals,
                           const int* __restrict__ oCnt,
                           const float* __restrict__ T2, const float* __restrict__ T1,
                           const float* __restrict__ dis, const float* __restrict__ b,
                           float* __restrict__ out, int relu) {
    int i = blockIdx.x, c = threadIdx.x;
    int cnt = oCnt[i];
    const int*   cols = oCols + (size_t)i * 2048;
    const float* vals = oVals + (size_t)i * 2048;
    float acc = 0.0f;
    for (int t = 0; t < cnt; t++) acc += vals[t] * T2[cols[t] * HID + c];
    float di = dis[i];
    float v = di * (acc + 2.0f * di * T1[i * HID + c]) + b[c];
    if (relu) v = fmaxf(v, 0.0f);
    out[i * HID + c] = v;
}

// ---------------- dense kernels ----------------

__global__ void k_encoder(const float* __restrict__ x, const float* __restrict__ W,
                          const float* __restrict__ b, float* __restrict__ h) {
    int i = blockIdx.x;
    int c = threadIdx.x;
    float acc = b[c];
#pragma unroll
    for (int k = 0; k < 16; k++) acc += x[i * 16 + k] * W[k * HID + c];
    h[i * HID + c] = acc;
}

// Split-K SGEMM with packed f32x2 FMAs. 64x64 tile, 256 threads, TM=TN=4.
// Writes raw partial sums for K-chunk blockIdx.z into P + z*M*N.
// REQUIRES: M,N multiples of 64; Kc multiple of 16; 16B-aligned pointers.
__global__ void k_gemm_sk(const float* __restrict__ A, const float* __restrict__ B,
                          float* __restrict__ P, int M, int N, int K, int Kc) {
    __shared__ float Asd[16][132];   // duplicated-A, padded
    __shared__ float Bs[16][64];
    int t = threadIdx.x;
    int m0 = blockIdx.y * 64, n0 = blockIdx.x * 64;
    int kBeg = blockIdx.z * Kc;
    int ar = t >> 2, ac = (t & 3) << 2;
    int bk = t >> 4, bn = (t & 15) << 2;
    int tm = (t >> 4) << 2, tn = (t & 15) << 2;

    unsigned long long acc[4][2];
#pragma unroll
    for (int a = 0; a < 4; a++) { acc[a][0] = 0ull; acc[a][1] = 0ull; }

    const float* Aptr = A + (size_t)(m0 + ar) * K + kBeg + ac;
    const float* Bptr = B + (size_t)(kBeg + bk) * N + n0 + bn;

    float4 av = *(const float4*)Aptr;
    float4 bv = *(const float4*)Bptr;
    for (int k0 = 0; k0 < Kc; k0 += 16) {
        *(float2*)&Asd[ac + 0][2 * ar] = make_float2(av.x, av.x);
        *(float2*)&Asd[ac + 1][2 * ar] = make_float2(av.y, av.y);
        *(float2*)&Asd[ac + 2][2 * ar] = make_float2(av.z, av.z);
        *(float2*)&Asd[ac + 3][2 * ar] = make_float2(av.w, av.w);
        *(float4*)&Bs[bk][bn] = bv;
        __syncthreads();
        if (k0 + 16 < Kc) {
            av = *(const float4*)(Aptr + k0 + 16);
            bv = *(const float4*)(Bptr + (size_t)(k0 + 16) * N);
        }
#pragma unroll
        for (int kk = 0; kk < 16; kk++) {
            ulonglong2 a01 = *(const ulonglong2*)&Asd[kk][2 * tm];
            ulonglong2 a23 = *(const ulonglong2*)&Asd[kk][2 * tm + 4];
            ulonglong2 b01 = *(const ulonglong2*)&Bs[kk][tn];
            ffma2(acc[0][0], a01.x, b01.x); ffma2(acc[0][1], a01.x, b01.y);
            ffma2(acc[1][0], a01.y, b01.x); ffma2(acc[1][1], a01.y, b01.y);
            ffma2(acc[2][0], a23.x, b01.x); ffma2(acc[2][1], a23.x, b01.y);
            ffma2(acc[3][0], a23.y, b01.x); ffma2(acc[3][1], a23.y, b01.y);
        }
        __syncthreads();
    }
    float* Pp = P + (size_t)blockIdx.z * M * N;
#pragma unroll
    for (int a = 0; a < 4; a++) {
        int gm = m0 + tm + a;
        float4 o;
        o.x = __uint_as_float((unsigned)acc[a][0]);
        o.y = __uint_as_float((unsigned)(acc[a][0] >> 32));
        o.z = __uint_as_float((unsigned)acc[a][1]);
        o.w = __uint_as_float((unsigned)(acc[a][1] >> 32));
        *(float4*)&Pp[(size_t)gm * N + n0 + tn] = o;
    }
}

// Reduce split-K partials + fused epilogue.
// mode 0: C = sum (T1); C2 = dis[row]*sum (T2)
// mode 1: C = sum, diag zeroed (augment)
// mode 2: C = [relu]( dis*(sum + 2*dis*C2in) + bias )   (C2 = T1 input)
__global__ void k_reduce(const float* __restrict__ P, int S, int M, int N, int mode,
                         const float* __restrict__ dis, const float* __restrict__ bias,
                         float* __restrict__ C, float* __restrict__ C2, int relu) {
    int idx = blockIdx.x * blockDim.x + threadIdx.x;
    int total = M * N;
    if (idx >= total) return;
    float s = 0.0f;
    for (int z = 0; z < S; z++) s += P[(size_t)z * total + idx];
    int gm = idx / N;
    int gn = idx - gm * N;
    if (mode == 0) {
        C[idx] = s;
        C2[idx] = dis[gm] * s;
    } else if (mode == 1) {
        C[idx] = (gm == gn) ? 0.0f : s;
    } else {
        float di = dis[gm];
        float v = di * (s + 2.0f * di * C2[idx]) + bias[gn];
        if (relu) v = fmaxf(v, 0.0f);
        C[idx] = v;
    }
}

__global__ void k_gather_rows4(const float* __restrict__ A, const int* __restrict__ perm,
                               float* __restrict__ P, int k, int n) {
    int q = blockIdx.x * blockDim.x + threadIdx.x;
    int tot = k * (n / 4);
    if (q >= tot) return;
    int r = q / (n / 4);
    int m4 = (q - r * (n / 4)) * 4;
    int pr = perm[r];
    float4 v = *(const float4*)(A + (size_t)pr * n + m4);
    if (pr >= m4 && pr < m4 + 4) ((float*)&v)[pr - m4] = 1.0f;
    *(float4*)(P + (size_t)q * 4) = v;
}

__global__ void k_gather_cols(const float* __restrict__ A, const int* __restrict__ perm,
                              float* __restrict__ Q, int k, int n) {
    size_t idx = (size_t)blockIdx.x * blockDim.x + threadIdx.x;
    if (idx < (size_t)n * k) {
        int m = (int)(idx / k), c = (int)(idx % k);
        int pc = perm[c];
        float v = A[(size_t)m * n + pc];
        Q[idx] = (m == pc) ? 1.0f : v;
    }
}

// dis[i] = rsqrt(rowsum - diag + 2); also zeroes diag (safe if already 0)
__global__ void k_dis_zd(float* __restrict__ A, float* __restrict__ dis, int n) {
    int i = blockIdx.x;
    const float4* row = (const float4*)(A + (size_t)i * n);
    float s = 0.0f;
    for (int j = threadIdx.x; j < n / 4; j += 256) {
        float4 v = row[j];
        s += v.x + v.y + v.z + v.w;
    }
    __shared__ float sm[256];
    sm[threadIdx.x] = s;
    __syncthreads();
    for (int o = 128; o; o >>= 1) {
        if (threadIdx.x < o) sm[threadIdx.x] += sm[threadIdx.x + o];
        __syncthreads();
    }
    if (threadIdx.x == 0) {
        float d = A[(size_t)i * n + i];
        dis[i] = rsqrtf(sm[0] - d + 2.0f);
        A[(size_t)i * n + i] = 0.0f;
    }
}

// ---------------- pooling ----------------

__global__ void k_pnorm(const float* __restrict__ p_pool, float* __restrict__ pn) {
    int r = blockIdx.x;
    float v = p_pool[r * HID + threadIdx.x];
    __shared__ float sm[HID];
    sm[threadIdx.x] = v * v;
    __syncthreads();
    for (int o = 64; o > 0; o >>= 1) {
        if (threadIdx.x < o) sm[threadIdx.x] += sm[threadIdx.x + o];
        __syncthreads();
    }
    if (threadIdx.x == 0) pn[r] = sqrtf(sm[0]);
}

__global__ void k_score(const float* __restrict__ h, const float* __restrict__ p,
                        const float* __restrict__ pn, int lvl, float* __restrict__ score) {
    int i = blockIdx.x;
    __shared__ float sm[HID];
    sm[threadIdx.x] = h[i * HID + threadIdx.x] * p[threadIdx.x];
    __syncthreads();
    for (int o = 64; o > 0; o >>= 1) {
        if (threadIdx.x < o) sm[threadIdx.x] += sm[threadIdx.x + o];
        __syncthreads();
    }
    if (threadIdx.x == 0) score[i] = sm[0] / pn[lvl];
}

// Packed-key bitonic sort (n/2 pair mapping); also fills perm, vals and inv.
__global__ void k_topk_sort(const float* __restrict__ score, int n, int k,
                            int* __restrict__ perm, float* __restrict__ vals,
                            int* __restrict__ inv) {
    __shared__ unsigned long long key[4096];
    int tid = threadIdx.x;
    for (int i = tid; i < n; i += blockDim.x) {
        unsigned u = __float_as_uint(score[i]);
        u = (u & 0x80000000u) ? ~u : (u | 0x80000000u);
        key[i] = ((unsigned long long)u << 32) | (unsigned)(~i);
        inv[i] = -1;
    }
    __syncthreads();
    int half = n >> 1;
    for (int ksz = 2; ksz <= n; ksz <<= 1) {
        for (int j = ksz >> 1; j > 0; j >>= 1) {
            for (int p = tid; p < half; p += blockDim.x) {
                int idx = ((p & ~(j - 1)) << 1) | (p & (j - 1));
                int ixj = idx | j;
                unsigned long long a = key[idx], b = key[ixj];
                bool dir = (idx & ksz) == 0;
                if (dir ? (b > a) : (a > b)) { key[idx] = b; key[ixj] = a; }
            }
            __syncthreads();
        }
    }
    for (int r = tid; r < k; r += blockDim.x) {
        int idx = (int)(~(unsigned)key[r]);
        perm[r] = idx;
        vals[r] = score[idx];
        inv[idx] = r;
    }
}

__global__ void k_pool(const float* __restrict__ h, const int* __restrict__ perm,
                       const float* __restrict__ vals, float* __restrict__ hp) {
    int r = blockIdx.x, c = threadIdx.x;
    hp[r * HID + c] = h[perm[r] * HID + c] * tanhf(vals[r]);
}

__global__ void k_unpool(const float* __restrict__ X, const float* __restrict__ h,
                         const int* __restrict__ inv, float* __restrict__ out) {
    int i = blockIdx.x, c = threadIdx.x;
    float v = X[i * HID + c];
    int r = inv[i];
    if (r >= 0) v += h[r * HID + c];
    out[i * HID + c] = v;
}

// ---------------- final conv ----------------

__global__ void k_hw_out(const float* __restrict__ h, const float* __restrict__ Wout,
                         const float* __restrict__ dis, float* __restrict__ hw,
                         float* __restrict__ g) {
    int i = blockIdx.x;
    __shared__ float sm[HID];
    sm[threadIdx.x] = h[i * HID + threadIdx.x] * Wout[threadIdx.x];
    __syncthreads();
    for (int o = 64; o > 0; o >>= 1) {
        if (threadIdx.x < o) sm[threadIdx.x] += sm[threadIdx.x + o];
        __syncthreads();
    }
    if (threadIdx.x == 0) { hw[i] = sm[0]; g[i] = dis[i] * sm[0]; }
}

__global__ void k_final_sp(const int* __restrict__ rp, const int* __restrict__ colA,
                           const float* __restrict__ g, const float* __restrict__ hw,
                           const float* __restrict__ dis, const float* __restrict__ b,
                           float* __restrict__ out) {
    int i = blockIdx.x * blockDim.x + threadIdx.x;
    if (i < N0) {
        float s = 0.0f;
        int a = rp[i], e = rp[i + 1];
        for (int t = a; t < e; t++) s += g[colA[t]];
        float di = dis[i];
        out[i] = di * (s + 2.0f * di * hw[i]) + b[0];
    }
}

// ---------------- host orchestration ----------------

static float* g_split = nullptr;

static void gemm_sk(const float* A, const float* B, int M, int N, int K, int S,
                    int mode, const float* dis, const float* bias,
                    float* C, float* C2, int relu) {
    dim3 g(N / 64, M / 64, S);
    k_gemm_sk<<<g, 256>>>(A, B, g_split, M, N, K, K / S);
    int total = M * N;
    k_reduce<<<(total + 255) / 256, 256>>>(g_split, S, M, N, mode, dis, bias, C, C2, relu);
}

static void gcn_dense(float* A, int n, const float* hin, const float* W, const float* b,
                      float* hout, int relu, float* T1, float* T2, float* dis,
                      bool computeDis, int S_hw, int S_at) {
    if (computeDis) k_dis_zd<<<n, 256>>>(A, dis, n);
    gemm_sk(hin, W, n, HID, HID, S_hw, 0, dis, nullptr, T1, T2, 0);
    gemm_sk(A, T2, n, HID, n, S_at, 2, dis, b, hout, T1, relu);
}

extern "C" void kernel_launch(void* const* d_in, const int* in_sizes, int n_in,
                              void* d_out, int out_size) {
    const float* x      = (const float*)d_in[0];
    const int*   ei     = (const int*)d_in[1];
    const float* W_enc  = (const float*)d_in[3];
    const float* b_enc  = (const float*)d_in[4];
    const float* W_down = (const float*)d_in[5];
    const float* b_down = (const float*)d_in[6];
    const float* W_up   = (const float*)d_in[7];
    const float* b_up   = (const float*)d_in[8];
    const float* W_out  = (const float*)d_in[9];
    const float* b_out  = (const float*)d_in[10];
    const float* p_pool = (const float*)d_in[11];
    float* out = (float*)d_out;

    float *A2, *A3, *A4, *Pb, *Qb;
    float *X0, *X1, *X2, *X3, *Ha, *Hb, *T1, *T2;
    float *Score, *Vals, *HWo, *Gv, *Pn;
    float *A1vals;
    int *A1cols, *A1cnt;
    int *P0, *P1, *P2, *P3, *Rp, *ColA, *Cnt, *Cur;
    int *I0, *I1, *I2, *I3;
    float *D0, *D1, *D2, *D3, *D4;
    cudaGetSymbolAddress((void**)&A1cols, dA1cols);
    cudaGetSymbolAddress((void**)&A1vals, dA1vals);
    cudaGetSymbolAddress((void**)&A1cnt, dA1cnt);
    cudaGetSymbolAddress((void**)&A2, dA2);
    cudaGetSymbolAddress((void**)&A3, dA3);
    cudaGetSymbolAddress((void**)&A4, dA4);
    cudaGetSymbolAddress((void**)&g_split, dSplit);
    cudaGetSymbolAddress((void**)&Pb, dPbuf);
    cudaGetSymbolAddress((void**)&Qb, dQbuf);
    cudaGetSymbolAddress((void**)&X0, dX0);
    cudaGetSymbolAddress((void**)&X1, dX1);
    cudaGetSymbolAddress((void**)&X2, dX2);
    cudaGetSymbolAddress((void**)&X3, dX3);
    cudaGetSymbolAddress((void**)&Ha, dHa);
    cudaGetSymbolAddress((void**)&Hb, dHb);
    cudaGetSymbolAddress((void**)&T1, dT1);
    cudaGetSymbolAddress((void**)&T2, dT2);
    cudaGetSymbolAddress((void**)&Score, dScore);
    cudaGetSymbolAddress((void**)&Vals, dValsArr);
    cudaGetSymbolAddress((void**)&HWo, dHWo);
    cudaGetSymbolAddress((void**)&Gv, dGv);
    cudaGetSymbolAddress((void**)&Pn, dPn);
    cudaGetSymbolAddress((void**)&P0, dPerm0);
    cudaGetSymbolAddress((void**)&P1, dPerm1);
    cudaGetSymbolAddress((void**)&P2, dPerm2);
    cudaGetSymbolAddress((void**)&P3, dPerm3);
    cudaGetSymbolAddress((void**)&I0, dInv0);
    cudaGetSymbolAddress((void**)&I1, dInv1);
    cudaGetSymbolAddress((void**)&I2, dInv2);
    cudaGetSymbolAddress((void**)&I3, dInv3);
    cudaGetSymbolAddress((void**)&D0, dDis0);
    cudaGetSymbolAddress((void**)&D1, dDis1);
    cudaGetSymbolAddress((void**)&D2, dDis2);
    cudaGetSymbolAddress((void**)&D3, dDis3);
    cudaGetSymbolAddress((void**)&D4, dDis4);
    cudaGetSymbolAddress((void**)&Rp, dRp);
    cudaGetSymbolAddress((void**)&ColA, dColA);
    cudaGetSymbolAddress((void**)&Cnt, dCnt);
    cudaGetSymbolAddress((void**)&Cur, dCur);

    const int ns[5] = {4096, 2048, 1024, 512, 256};
    float* Xs[4] = {X0, X1, X2, X3};
    int*   Ps[4] = {P0, P1, P2, P3};
    int*   Is[4] = {I0, I1, I2, I3};
    // split factors: S_hw per node count, S_at per node count
    auto S_hw = [](int n) { return n >= 4096 ? 1 : (n >= 2048 ? 2 : (n >= 1024 ? 4 : 8)); };
    auto S_at = [](int n) { return n >= 1024 ? 8 : 16; };

    // 1) node encoder
    k_encoder<<<N0, HID>>>(x, W_enc, b_enc, Ha);

    // 2) CSR of A0
    k_zero2<<<N0 / 256, 256>>>(Cnt, Cur, N0);
    k_count<<<EDGES / 256, 256>>>(ei, Cnt);
    k_scan<<<1, 1024>>>(Cnt, Rp);
    k_fill<<<EDGES / 256, 256>>>(ei, Rp, Cur, ColA);
    k_dis0<<<N0 / 256, 256>>>(Cnt, D0);

    // 3) pool vector norms
    k_pnorm<<<4, HID>>>(p_pool, Pn);

    // 4) down conv 0 (sparse)
    gemm_sk(Ha, W_down, N0, HID, HID, 1, 0, D0, nullptr, T1, T2, 0);
    k_spmm0_ep<<<N0, HID>>>(Rp, ColA, T2, T1, D0, b_down, X0, 1);

    // 5) down path
    const float* hprev = X0;
    for (int i = 1; i <= 4; i++) {
        int n = ns[i - 1], k = ns[i];
        k_score<<<n, HID>>>(hprev, p_pool + (size_t)(i - 1) * HID, Pn, i - 1, Score);
        k_topk_sort<<<1, 1024>>>(Score, n, k, Ps[i - 1], Vals, Is[i - 1]);
        k_pool<<<k, HID>>>(hprev, Ps[i - 1], Vals, Ha);

        float* hout = (i < 4) ? Xs[i] : Hb;
        const float* W = W_down + (size_t)i * HID * HID;
        const float* b = b_down + (size_t)i * HID;

        if (i == 1) {
            k_spgemm1<<<k, 256>>>(Rp, ColA, Ps[0], I0, A1cols, A1vals, A1cnt, D1);
            gemm_sk(Ha, W, k, HID, HID, S_hw(k), 0, D1, nullptr, T1, T2, 0);
            k_spmm1_ep<<<k, HID>>>(A1cols, A1vals, A1cnt, T2, T1, D1, b, hout, 1);
        } else if (i == 2) {
            k_spgemm2<<<k, 256>>>(A1cols, A1vals, A1cnt, Ps[1], I1, A2, D2, k);
            gcn_dense(A2, k, Ha, W, b, hout, 1, T1, T2, D2, false, S_hw(k), S_at(k));
        } else {
            float* Aprev = (i == 3) ? A2 : A3;
            float* Acur = (i == 3) ? A3 : A4;
            float* Dcur = (i == 3) ? D3 : D4;
            int tot4 = k * (n / 4);
            k_gather_rows4<<<(tot4 + 255) / 256, 256>>>(Aprev, Ps[i - 1], Pb, k, n);
            size_t t = (size_t)k * n;
            k_gather_cols<<<(unsigned)((t + 255) / 256), 256>>>(Aprev, Ps[i - 1], Qb, k, n);
            int Saug = (i == 3) ? 4 : 16;
            gemm_sk(Pb, Qb, k, k, n, Saug, 1, nullptr, nullptr, Acur, nullptr, 0);
            gcn_dense(Acur, k, Ha, W, b, hout, 1, T1, T2, Dcur, true, S_hw(k), S_at(k));
        }
        hprev = hout;
    }

    // 6) up path
    float* Dsv[4] = {D0, D1, D2, D3};
    float* hcur = Hb;
    for (int i = 0; i < 4; i++) {
        int j = 3 - i;
        int n = ns[j];
        k_unpool<<<n, HID>>>(Xs[j], hcur, Is[j], Ha);
        if (j >= 2) {
            gcn_dense(j == 2 ? A2 : A3, n, Ha, W_up + (size_t)i * HID * HID,
                      b_up + (size_t)i * HID, Hb, 1, T1, T2, Dsv[j], false,
                      S_hw(n), S_at(n));
            hcur = Hb;
        } else if (j == 1) {
            gemm_sk(Ha, W_up + (size_t)i * HID * HID, n, HID, HID, S_hw(n), 0,
                    D1, nullptr, T1, T2, 0);
            k_spmm1_ep<<<n, HID>>>(A1cols, A1vals, A1cnt, T2, T1, D1,
                                   b_up + (size_t)i * HID, Hb, 1);
            hcur = Hb;
        } else {
            k_hw_out<<<n, HID>>>(Ha, W_out, D0, HWo, Gv);
            k_final_sp<<<(n + 127) / 128, 128>>>(Rp, ColA, Gv, HWo, D0, b_out, out);
        }
    }
}